// round 13
// baseline (speedup 1.0000x reference)
#include <cuda_runtime.h>
#include <math.h>

// ---------------------------------------------------------------------------
// DWFormerBlock round 13: single-barrier multistage mainloop in the GEMM
// (wait -> barrier -> issue -> compute), and active-list + ping-pong +
// single-barrier phase 1 in fused attention. Same math as R12.
// ---------------------------------------------------------------------------

constexpr int cB  = 16;
constexpr int cT  = 768;
constexpr int cF  = 512;
constexpr int cFF = 2048;
constexpr int cH  = 8;
constexpr int cDH = 64;
constexpr int BT  = cB * cT;       // 12288
constexpr float NEGVAL = -1e30f;

constexpr int QT   = 64;
constexpr int KBL  = 64;
constexpr int NQT  = cT / QT;      // 12
constexpr int NBLK = cT / KBL;     // 12
constexpr int SQ   = 3 * cF;       // 1536

constexpr long OFF_QKV = 0;
constexpr long OFF_WO  = (long)cF * SQ;
constexpr long OFF_W1  = OFF_WO + (long)cF * cF;
constexpr long OFF_W2  = OFF_W1 + (long)cF * cFF;
constexpr long WSET    = OFF_W2 + (long)cFF * cF;

// ------------------------------- scratch -----------------------------------
__device__ float g_xl  [BT * cF];
__device__ float g_qkv [(long)BT * SQ];
__device__ float g_ao  [BT * cF];
__device__ float g_pj  [BT * cF];
__device__ float g_y   [BT * cF];
__device__ float g_h   [BT * cFF];
__device__ float g_lx  [BT * cF];
__device__ float g_gy  [BT * cF];
__device__ float g_pre [BT * cF];
__device__ float g_ls  [BT];
__device__ float g_h2  [BT];
__device__ float g_wise[BT];
__device__ float g_cp  [(long)cB * cH * NQT * cT];
__device__ float g_wt  [2 * WSET];
__device__ int   g_wid [BT];
__device__ int   g_nb  [cB];
__device__ int   g_ws  [cB * (cT + 1)];

// --------------------------- small helpers ---------------------------------
__device__ __forceinline__ unsigned tf32r(float f) {
    unsigned u;
    asm("cvt.rna.tf32.f32 %0, %1;" : "=r"(u) : "f"(f));
    return u;
}
__device__ __forceinline__ float tf32f(float f) {
    return __uint_as_float(tf32r(f));
}

__device__ __forceinline__ void mma_tf32(float& d0, float& d1, float& d2, float& d3,
                                         unsigned a0, unsigned a1, unsigned a2, unsigned a3,
                                         unsigned b0, unsigned b1) {
    asm volatile(
        "mma.sync.aligned.m16n8k8.row.col.f32.tf32.tf32.f32 "
        "{%0,%1,%2,%3}, {%4,%5,%6,%7}, {%8,%9}, {%0,%1,%2,%3};"
        : "+f"(d0), "+f"(d1), "+f"(d2), "+f"(d3)
        : "r"(a0), "r"(a1), "r"(a2), "r"(a3), "r"(b0), "r"(b1));
}

__device__ __forceinline__ void cpasync16(void* sdst, const void* gsrc) {
    unsigned s = (unsigned)__cvta_generic_to_shared(sdst);
    asm volatile("cp.async.cg.shared.global [%0], [%1], 16;" :: "r"(s), "l"(gsrc));
}
__device__ __forceinline__ void cp_commit() {
    asm volatile("cp.async.commit_group;");
}
template <int N>
__device__ __forceinline__ void cp_wait() {
    asm volatile("cp.async.wait_group %0;" :: "n"(N));
}

__device__ __forceinline__ float redMax256(float v) {
    __shared__ float sm[8];
#pragma unroll
    for (int o = 16; o > 0; o >>= 1) v = fmaxf(v, __shfl_xor_sync(0xffffffffu, v, o));
    if ((threadIdx.x & 31) == 0) sm[threadIdx.x >> 5] = v;
    __syncthreads();
    if (threadIdx.x == 0) {
        float m = sm[0];
#pragma unroll
        for (int i = 1; i < 8; i++) m = fmaxf(m, sm[i]);
        sm[0] = m;
    }
    __syncthreads();
    float r = sm[0];
    __syncthreads();
    return r;
}

__device__ __forceinline__ float redSum256(float v) {
    __shared__ float sm[8];
#pragma unroll
    for (int o = 16; o > 0; o >>= 1) v += __shfl_xor_sync(0xffffffffu, v, o);
    if ((threadIdx.x & 31) == 0) sm[threadIdx.x >> 5] = v;
    __syncthreads();
    if (threadIdx.x == 0) {
        float s = 0.f;
#pragma unroll
        for (int i = 0; i < 8; i++) s += sm[i];
        sm[0] = s;
    }
    __syncthreads();
    float r = sm[0];
    __syncthreads();
    return r;
}

// ----------------------- packed weight tf32 conversion ---------------------
struct WSrc { const float* p[12]; };

__global__ void cvtw_all(WSrc ws, float* __restrict__ dst) {
    int j = blockIdx.y;
    int i = blockIdx.x * 256 + threadIdx.x;
    int t = j / 6, jj = j % 6;
    long tb = (long)t * WSET;
    const float* src = ws.p[j];
    if (jj < 3) {
        if (i < cF * cF) {
            int r = i >> 9, c = i & 511;
            dst[tb + OFF_QKV + (long)r * SQ + jj * cF + c] = tf32f(src[i]);
        }
    } else if (jj == 3) {
        if (i < cF * cF)  dst[tb + OFF_WO + i] = tf32f(src[i]);
    } else if (jj == 4) {
        if (i < cF * cFF) dst[tb + OFF_W1 + i] = tf32f(src[i]);
    } else {
        if (i < cFF * cF) dst[tb + OFF_W2 + i] = tf32f(src[i]);
    }
}

// ------------------------------- masks kernel ------------------------------
__global__ void masks_kernel(const float* __restrict__ hs, const float* __restrict__ msk,
                             float* __restrict__ thr_out, int* __restrict__ wid,
                             int* __restrict__ nbarr, int* __restrict__ ws,
                             float* __restrict__ wise) {
    int b = blockIdx.x, tid = threadIdx.x;
    __shared__ float ss[1024];
    __shared__ int a1[cT];
    __shared__ int x3[cT];
    __shared__ float red[256];
    __shared__ float sthr;

    for (int i = tid; i < 1024; i += 256)
        ss[i] = (i < cT) ? hs[b * cT + i] : 3.402823466e38f;
    __syncthreads();

    for (int k2 = 2; k2 <= 1024; k2 <<= 1) {
        for (int j = k2 >> 1; j > 0; j >>= 1) {
            for (int i = tid; i < 1024; i += 256) {
                int l = i ^ j;
                if (l > i) {
                    float a = ss[i], c = ss[l];
                    bool up = ((i & k2) == 0);
                    if ((a > c) == up) { ss[i] = c; ss[l] = a; }
                }
            }
            __syncthreads();
        }
    }

    float m1 = 0.f;
    for (int i = tid; i < cT; i += 256) m1 += 1.0f - msk[b * cT + i];
    red[tid] = m1; __syncthreads();
    for (int s = 128; s > 0; s >>= 1) {
        if (tid < s) red[tid] += red[tid + s];
        __syncthreads();
    }
    if (tid == 0) {
        float mm = red[0];
        int med = (int)(mm * 0.5f + (float)cT - mm);
        if (med > cT - 1) med = cT - 1;
        if (med < 0) med = 0;
        sthr = ss[med];
        thr_out[b] = sthr;
    }
    __syncthreads();
    float thr = sthr;

    for (int i = tid; i < cT; i += 256) {
        int keep = (hs[b * cT + i] >= thr) ? 1 : 0;
        a1[i] = keep;
        wise[b * cT + i] = keep ? 1.0f : 0.85f;
    }
    __syncthreads();
    for (int i = tid; i < cT; i += 256) {
        int x2 = (i < cT - 1) ? a1[i + 1] : (1 - a1[cT - 1]);
        x3[i] = (x2 != a1[i]) ? 1 : 0;
    }
    __syncthreads();
    if (tid == 0) {
        int c = 0;
        ws[b * (cT + 1)] = 0;
        int prev = 0;
        for (int t = 0; t < cT; t++) {
            int xt = x3[t];
            int xm = (xt == 1 && prev == 1) ? 0 : xt;
            if (t == cT - 1) xm = 1;
            prev = xt;
            wid[b * cT + t] = c;
            if (xm) { c++; ws[b * (cT + 1) + c] = t + 1; }
        }
        nbarr[b] = c;
    }
}

// ------------------------------ layernorm ----------------------------------
__global__ void ln_kernel(const float* __restrict__ X, const float* __restrict__ R,
                          float* __restrict__ Y, int rnd) {
    long row = blockIdx.x;
    float4 v = ((const float4*)(X + row * cF))[threadIdx.x];
    if (R) {
        float4 r = ((const float4*)(R + row * cF))[threadIdx.x];
        v.x += r.x; v.y += r.y; v.z += r.z; v.w += r.w;
    }
    float s = v.x + v.y + v.z + v.w;
    float q = v.x * v.x + v.y * v.y + v.z * v.z + v.w * v.w;
    __shared__ float rs[4], rq[4];
#pragma unroll
    for (int o = 16; o > 0; o >>= 1) {
        s += __shfl_down_sync(0xffffffffu, s, o);
        q += __shfl_down_sync(0xffffffffu, q, o);
    }
    int w = threadIdx.x >> 5;
    if ((threadIdx.x & 31) == 0) { rs[w] = s; rq[w] = q; }
    __syncthreads();
    s = rs[0] + rs[1] + rs[2] + rs[3];
    q = rq[0] + rq[1] + rq[2] + rq[3];
    float mean = s * (1.0f / cF);
    float var  = q * (1.0f / cF) - mean * mean;
    float inv  = rsqrtf(var + 1e-5f);
    float4 o4 = make_float4((v.x - mean) * inv, (v.y - mean) * inv,
                            (v.z - mean) * inv, (v.w - mean) * inv);
    if (rnd) {
        o4.x = tf32f(o4.x); o4.y = tf32f(o4.y);
        o4.z = tf32f(o4.z); o4.w = tf32f(o4.w);
    }
    ((float4*)(Y + row * cF))[threadIdx.x] = o4;
}

// --------------------------- TF32 tensor GEMM (cp.async) -------------------
// NT=128, WM=2 x WN=2 (64x64 warp tiles). Single-barrier multistage loop:
// wait(own groups) -> barrier (publish stage it, close compute it-1) ->
// issue stage it+1 (overwrites buffer retired at it-1) -> compute stage it.
template <int BM, int BN, int NT, int WM, int WN, bool RELU, bool ROUND>
__global__ void __launch_bounds__(NT, 2)
gemm_as(const float* __restrict__ A, const float* __restrict__ Bm, float* __restrict__ C,
        int K, int lda, int ldb, int ldc, float alpha) {
    constexpr int BK  = 16;
    constexpr int BKP = BK + 4;
    constexpr int BNP = BN + 8;
    constexpr int MT  = BM / WM / 16;
    constexpr int NTT = BN / WN / 8;
    constexpr int AI  = BM * BK / 4 / NT;
    constexpr int BI  = BN * BK / 4 / NT;
    static_assert(AI * NT * 4 == BM * BK, "A tile");
    static_assert(BI * NT * 4 == BN * BK, "B tile");

    __shared__ float As[2][BM][BKP];
    __shared__ float Bs[2][BK][BNP];

    int tid  = threadIdx.x;
    int wid  = tid >> 5, lane = tid & 31;
    int g    = lane >> 2, c = lane & 3;
    int wm0  = (wid % WM) * (BM / WM);
    int wn0  = (wid / WM) * (BN / WN);
    int m0   = blockIdx.y * BM, n0 = blockIdx.x * BN;

    float acc[MT][NTT][4] = {};

    auto issue = [&](int s, int k0) {
#pragma unroll
        for (int i = 0; i < AI; i++) {
            int e = tid + i * NT;
            int m = e >> 2, kq = (e & 3) << 2;
            cpasync16(&As[s][m][kq], A + (long)(m0 + m) * lda + k0 + kq);
        }
#pragma unroll
        for (int i = 0; i < BI; i++) {
            int e = tid + i * NT;
            int kk = e / (BN / 4), nq = (e % (BN / 4)) * 4;
            cpasync16(&Bs[s][kk][nq], Bm + (long)(k0 + kk) * ldb + n0 + nq);
        }
        cp_commit();
    };

    int KT = K / BK;
    issue(0, 0);

    for (int it = 0; it < KT; it++) {
        cp_wait<0>();
        __syncthreads();
        if (it + 1 < KT) issue((it + 1) & 1, (it + 1) * BK);

        int buf = it & 1;
#pragma unroll
        for (int kk = 0; kk < BK; kk += 8) {
            unsigned af[MT][4];
#pragma unroll
            for (int i = 0; i < MT; i++) {
                int r0 = wm0 + i * 16 + g;
                af[i][0] = __float_as_uint(As[buf][r0][kk + c]);
                af[i][1] = __float_as_uint(As[buf][r0 + 8][kk + c]);
                af[i][2] = __float_as_uint(As[buf][r0][kk + c + 4]);
                af[i][3] = __float_as_uint(As[buf][r0 + 8][kk + c + 4]);
            }
            unsigned bf[NTT][2];
#pragma unroll
            for (int j = 0; j < NTT; j++) {
                int n = wn0 + j * 8 + g;
                bf[j][0] = __float_as_uint(Bs[buf][kk + c][n]);
                bf[j][1] = __float_as_uint(Bs[buf][kk + c + 4][n]);
            }
#pragma unroll
            for (int i = 0; i < MT; i++)
#pragma unroll
                for (int j = 0; j < NTT; j++)
                    mma_tf32(acc[i][j][0], acc[i][j][1], acc[i][j][2], acc[i][j][3],
                             af[i][0], af[i][1], af[i][2], af[i][3],
                             bf[j][0], bf[j][1]);
        }
    }

#pragma unroll
    for (int i = 0; i < MT; i++) {
#pragma unroll
        for (int j = 0; j < NTT; j++) {
            int row0 = m0 + wm0 + i * 16 + g;
            int col  = n0 + wn0 + j * 8 + c * 2;
            float vals[4];
#pragma unroll
            for (int t = 0; t < 4; t++) {
                float vv = acc[i][j][t] * alpha;
                if (RELU)  vv = fmaxf(vv, 0.f);
                if (ROUND) vv = tf32f(vv);
                vals[t] = vv;
            }
            *(float2*)(C + (long)row0 * ldc + col)       = make_float2(vals[0], vals[1]);
            *(float2*)(C + (long)(row0 + 8) * ldc + col) = make_float2(vals[2], vals[3]);
        }
    }
}

// ------------------------ fused attention kernel ---------------------------
// Active-block list (CTA-uniform, precomputed) + ping-pong K buffers with a
// single barrier per block in phase 1. Phase 2 unchanged from R12.
__global__ void __launch_bounds__(128, 2)
attn_fused(const float* __restrict__ QKV, float* __restrict__ AO,
           float* __restrict__ colpart,
           const int* __restrict__ widp, const int* __restrict__ nbp, int mode) {
    __shared__ float pool[8960];
    __shared__ float red[2][QT];
    __shared__ float sm_t[QT];
    __shared__ int   wq_s[QT], wk_s[2][KBL];
    __shared__ int   act[NBLK], actflag[NBLK], s_cnt;

    float (*B0)[68] = (float(*)[68])pool;
    float (*B1)[68] = (float(*)[68])(pool + 4352);
    float (*Vs)[72] = (float(*)[72])(pool + 4352);

    int qt = blockIdx.x, bh = blockIdx.y;
    int b = bh >> 3;
    int tid = threadIdx.x, wid = tid >> 5, lane = tid & 31;
    int g = lane >> 2, c = lane & 3;
    int wq0 = (wid & 1) * 32;
    int wk0 = (wid >> 1) * 32;
    int kgrp = wid >> 1;
    int q0 = qt * QT;
    long base = (long)b * cT * SQ + (bh & 7) * cDH;
    const float* Qp = QKV + base;
    const float* Kp = QKV + base + cF;
    const float* Vp = QKV + base + 2 * cF;
    int nbv = (mode == 1) ? __ldg(&nbp[b]) : 0;

    // ---- stage Q tile; thread 0 builds active-block list ----
#pragma unroll
    for (int i = 0; i < 8; i++) {
        int e = tid + i * 128;
        int r = e >> 4, cq = (e & 15) << 2;
        cpasync16(&B0[r][cq], Qp + (long)(q0 + r) * SQ + cq);
    }
    cp_commit();
    if (mode == 0 && tid < QT) wq_s[tid] = __ldg(&widp[b * cT + q0 + tid]);
    if (tid == 0) {
        int cnt = 0;
        if (mode == 0) {
            int wq_lo = __ldg(&widp[b * cT + q0]);
            int wq_hi = __ldg(&widp[b * cT + q0 + QT - 1]);
            for (int kb = 0; kb < NBLK; kb++) {
                int klo = __ldg(&widp[b * cT + kb * KBL]);
                int khi = __ldg(&widp[b * cT + kb * KBL + KBL - 1]);
                int a = (klo <= wq_hi) && (khi >= wq_lo);
                actflag[kb] = a;
                if (a) act[cnt++] = kb;
            }
        } else {
            for (int kb = 0; kb < NBLK; kb++) {
                int a = (kb * KBL < nbv);
                actflag[kb] = a;
                if (a) act[cnt++] = kb;
            }
        }
        s_cnt = cnt;
    }
    cp_wait<0>();
    __syncthreads();

    unsigned aq[2][8][4];
#pragma unroll
    for (int i = 0; i < 2; i++) {
        int r0 = wq0 + i * 16 + g;
#pragma unroll
        for (int kk = 0; kk < 8; kk++) {
            aq[i][kk][0] = __float_as_uint(B0[r0][kk * 8 + c]);
            aq[i][kk][1] = __float_as_uint(B0[r0 + 8][kk * 8 + c]);
            aq[i][kk][2] = __float_as_uint(B0[r0][kk * 8 + c + 4]);
            aq[i][kk][3] = __float_as_uint(B0[r0 + 8][kk * 8 + c + 4]);
        }
    }
    int cnt = s_cnt;
    __syncthreads();          // all warps done reading Q from B0

    auto issueK = [&](int s, int kb) {
        float (*dst)[68] = s ? B1 : B0;
#pragma unroll
        for (int i = 0; i < 8; i++) {
            int e = tid + i * 128;
            int r = e >> 4, cq = (e & 15) << 2;
            cpasync16(&dst[r][cq], Kp + (long)(kb * KBL + r) * SQ + cq);
        }
        cp_commit();
        if (mode == 0 && tid < KBL)
            wk_s[s][tid] = __ldg(&widp[b * cT + kb * KBL + tid]);
    };

    // ---- phase 1: row denominators over active blocks (1 barrier/block) ----
    float rsum[4] = {};
    if (cnt > 0) {
        issueK(0, act[0]);
        for (int ii = 0; ii < cnt; ii++) {
            cp_wait<0>();
            __syncthreads();
            if (ii + 1 < cnt) issueK((ii + 1) & 1, act[ii + 1]);

            int kb = act[ii];
            float (*Kb)[68] = (ii & 1) ? B1 : B0;
            const int* wk = wk_s[ii & 1];
            float sacc[2][4][4] = {};
#pragma unroll
            for (int kk = 0; kk < 8; kk++) {
                unsigned bf[4][2];
#pragma unroll
                for (int j = 0; j < 4; j++) {
                    int n = wk0 + j * 8 + g;
                    bf[j][0] = __float_as_uint(Kb[n][kk * 8 + c]);
                    bf[j][1] = __float_as_uint(Kb[n][kk * 8 + c + 4]);
                }
#pragma unroll
                for (int i = 0; i < 2; i++)
#pragma unroll
                    for (int j = 0; j < 4; j++)
                        mma_tf32(sacc[i][j][0], sacc[i][j][1], sacc[i][j][2], sacc[i][j][3],
                                 aq[i][kk][0], aq[i][kk][1], aq[i][kk][2], aq[i][kk][3],
                                 bf[j][0], bf[j][1]);
            }
#pragma unroll
            for (int i = 0; i < 2; i++)
#pragma unroll
                for (int j = 0; j < 4; j++)
#pragma unroll
                    for (int e = 0; e < 4; e++) {
                        float s = sacc[i][j][e] * 0.125f;
                        int qr = wq0 + i * 16 + g + ((e >> 1) ? 8 : 0);
                        int kc = wk0 + j * 8 + 2 * c + (e & 1);
                        bool msk = (mode == 0) ? (wk[kc] != wq_s[qr])
                                               : (kb * KBL + kc >= nbv);
                        int ri = i * 2 + (e >> 1);
                        if (!msk) rsum[ri] += __expf(s);
                    }
        }
    }
#pragma unroll
    for (int r = 0; r < 4; r++) {
        rsum[r] += __shfl_xor_sync(0xffffffffu, rsum[r], 1);
        rsum[r] += __shfl_xor_sync(0xffffffffu, rsum[r], 2);
    }
    __syncthreads();          // close phase-1 buffer reads before red[] reuse
    if (c == 0) {
#pragma unroll
        for (int r = 0; r < 4; r++)
            red[kgrp][wq0 + (r >> 1) * 16 + g + ((r & 1) ? 8 : 0)] = rsum[r];
    }
    __syncthreads();
    if (tid < QT) sm_t[tid] = 1.0f / (red[0][tid] + red[1][tid]);
    __syncthreads();

    // ---- phase 2: A, colsums, out (active blocks only) ----
    float oacc[2][4][4] = {};
    for (int kb = 0; kb < NBLK; kb++) {
        if (!actflag[kb]) {
            if (tid < KBL)
                colpart[((long)bh * NQT + qt) * cT + kb * KBL + tid] = 0.f;
            continue;
        }
#pragma unroll
        for (int i = 0; i < 8; i++) {
            int e = tid + i * 128;
            int r = e >> 4, cq = (e & 15) << 2;
            cpasync16(&B0[r][cq], Kp + (long)(kb * KBL + r) * SQ + cq);
            cpasync16(&Vs[r][cq], Vp + (long)(kb * KBL + r) * SQ + cq);
        }
        cp_commit();
        if (mode == 0 && tid < KBL) wk_s[0][tid] = __ldg(&widp[b * cT + kb * KBL + tid]);
        cp_wait<0>();
        __syncthreads();

        float sacc[2][4][4] = {};
#pragma unroll
        for (int kk = 0; kk < 8; kk++) {
            unsigned bf[4][2];
#pragma unroll
            for (int j = 0; j < 4; j++) {
                int n = wk0 + j * 8 + g;
                bf[j][0] = __float_as_uint(B0[n][kk * 8 + c]);
                bf[j][1] = __float_as_uint(B0[n][kk * 8 + c + 4]);
            }
#pragma unroll
            for (int i = 0; i < 2; i++)
#pragma unroll
                for (int j = 0; j < 4; j++)
                    mma_tf32(sacc[i][j][0], sacc[i][j][1], sacc[i][j][2], sacc[i][j][3],
                             aq[i][kk][0], aq[i][kk][1], aq[i][kk][2], aq[i][kk][3],
                             bf[j][0], bf[j][1]);
        }
        float idr[4];
#pragma unroll
        for (int r = 0; r < 4; r++)
            idr[r] = sm_t[wq0 + (r >> 1) * 16 + g + ((r & 1) ? 8 : 0)];
#pragma unroll
        for (int i = 0; i < 2; i++)
#pragma unroll
            for (int j = 0; j < 4; j++)
#pragma unroll
                for (int e = 0; e < 4; e++) {
                    float s = sacc[i][j][e] * 0.125f;
                    int qr = wq0 + i * 16 + g + ((e >> 1) ? 8 : 0);
                    int kc = wk0 + j * 8 + 2 * c + (e & 1);
                    bool msk = (mode == 0) ? (wk_s[0][kc] != wq_s[qr])
                                           : (kb * KBL + kc >= nbv);
                    int ri = i * 2 + (e >> 1);
                    float ev = msk ? 0.f : __expf(s);
                    sacc[i][j][e] = tf32f(ev * idr[ri]);
                }
        __syncthreads();
#pragma unroll
        for (int i = 0; i < 2; i++)
#pragma unroll
            for (int j = 0; j < 4; j++) {
                int qr = wq0 + i * 16 + g;
                int kc = wk0 + j * 8 + 2 * c;
                *(float2*)&B0[qr][kc]     = make_float2(sacc[i][j][0], sacc[i][j][1]);
                *(float2*)&B0[qr + 8][kc] = make_float2(sacc[i][j][2], sacc[i][j][3]);
            }
        __syncthreads();
        if (tid < KBL) {
            float cs = 0.f;
#pragma unroll 8
            for (int qq = 0; qq < QT; qq++) cs += B0[qq][tid];
            colpart[((long)bh * NQT + qt) * cT + kb * KBL + tid] = cs;
        }
#pragma unroll
        for (int kk = 0; kk < 8; kk++) {
            unsigned af[2][4], bf[4][2];
#pragma unroll
            for (int i = 0; i < 2; i++) {
                int r0 = wq0 + i * 16 + g;
                af[i][0] = __float_as_uint(B0[r0][kk * 8 + c]);
                af[i][1] = __float_as_uint(B0[r0 + 8][kk * 8 + c]);
                af[i][2] = __float_as_uint(B0[r0][kk * 8 + c + 4]);
                af[i][3] = __float_as_uint(B0[r0 + 8][kk * 8 + c + 4]);
            }
#pragma unroll
            for (int j = 0; j < 4; j++) {
                int n = wk0 + j * 8 + g;
                bf[j][0] = __float_as_uint(Vs[kk * 8 + c][n]);
                bf[j][1] = __float_as_uint(Vs[kk * 8 + c + 4][n]);
            }
#pragma unroll
            for (int i = 0; i < 2; i++)
#pragma unroll
                for (int j = 0; j < 4; j++)
                    mma_tf32(oacc[i][j][0], oacc[i][j][1], oacc[i][j][2], oacc[i][j][3],
                             af[i][0], af[i][1], af[i][2], af[i][3],
                             bf[j][0], bf[j][1]);
        }
        __syncthreads();
    }

#pragma unroll
    for (int i = 0; i < 2; i++)
#pragma unroll
        for (int j = 0; j < 4; j++) {
            int qg = q0 + wq0 + i * 16 + g;
            int dh = wk0 + j * 8 + 2 * c;
            long o0 = ((long)b * cT + qg) * cF + (bh & 7) * cDH + dh;
            *(float2*)&AO[o0] =
                make_float2(tf32f(oacc[i][j][0]), tf32f(oacc[i][j][1]));
            *(float2*)&AO[o0 + 8L * cF] =
                make_float2(tf32f(oacc[i][j][2]), tf32f(oacc[i][j][3]));
        }
}

// -------------------- colsum partial reduction -> score --------------------
__global__ void colreduce(const float* __restrict__ cp, float* __restrict__ outv,
                          float scale) {
    int t = blockIdx.x * 256 + threadIdx.x;
    if (t >= BT) return;
    int b = t / cT, k = t - b * cT;
    float s = 0.f;
    for (int h = 0; h < cH; h++)
#pragma unroll
        for (int q = 0; q < NQT; q++)
            s += cp[(((long)(b * cH + h)) * NQT + q) * cT + k];
    outv[t] = s * scale;
}

// ------------------- window aggregation: pre[b,w,:] ------------------------
__global__ void pre_kernel(const float* __restrict__ lx, const float* __restrict__ ls,
                           const int* __restrict__ nbarr, const int* __restrict__ ws,
                           float* __restrict__ pre) {
    int b = blockIdx.y, w = blockIdx.x, tid = threadIdx.x;
    float4 acc = make_float4(0.f, 0.f, 0.f, 0.f);
    if (w < nbarr[b]) {
        int s = ws[b * (cT + 1) + w];
        int e = ws[b * (cT + 1) + w + 1];
        for (int t = s; t < e; t++) {
            float sc = __ldg(&ls[b * cT + t]);
            float4 v = ((const float4*)(lx + ((long)b * cT + t) * cF))[tid];
            acc.x = fmaf(v.x, sc, acc.x); acc.y = fmaf(v.y, sc, acc.y);
            acc.z = fmaf(v.z, sc, acc.z); acc.w = fmaf(v.w, sc, acc.w);
        }
    }
    ((float4*)(pre + ((long)b * cT + w) * cF))[tid] = acc;
}

// --------------------------- misc elementwise ------------------------------
__global__ void scale_kernel(float* __restrict__ yx, const float* __restrict__ wise) {
    long row = blockIdx.x;
    float sc = wise[row];
    float4 v = ((const float4*)(yx + row * cF))[threadIdx.x];
    v.x *= sc; v.y *= sc; v.z *= sc; v.w *= sc;
    ((float4*)(yx + row * cF))[threadIdx.x] = v;
}

__global__ void final_data(const float* __restrict__ lx, const float* __restrict__ gy,
                           const int* __restrict__ wid, float* __restrict__ outd) {
    long i = blockIdx.x;
    int b = (int)(i / cT);
    int w = wid[i];
    float4 a = ((const float4*)(lx + i * cF))[threadIdx.x];
    float4 g = ((const float4*)(gy + ((long)b * cT + w) * cF))[threadIdx.x];
    a.x += g.x; a.y += g.y; a.z += g.z; a.w += g.w;
    ((float4*)(outd + i * cF))[threadIdx.x] = a;
}

__global__ void final_attn(const float* __restrict__ ls, const float* __restrict__ h2,
                           const int* __restrict__ wid, float* __restrict__ outa) {
    int b = blockIdx.x, tid = threadIdx.x;
    float xv[3];
#pragma unroll
    for (int i = 0; i < 3; i++) {
        int t = tid + i * 256;
        xv[i] = ls[b * cT + t] * h2[b * cT + wid[b * cT + t]];
    }
    float mx = redMax256(fmaxf(fmaxf(xv[0], xv[1]), xv[2]));
    float e[3];
    float s = 0.f;
#pragma unroll
    for (int i = 0; i < 3; i++) { e[i] = expf(xv[i] - mx); s += e[i]; }
    s = redSum256(s);
    float inv = 1.0f / s;
#pragma unroll
    for (int i = 0; i < 3; i++) outa[b * cT + tid + i * 256] = e[i] * inv;
}

// ------------------------------ host side ----------------------------------
static void run_transformer(const float* xin, const float* wset,
                            float* yout, float* score, int mode,
                            float* qkv, float* ao, float* pj, float* y, float* h,
                            float* colpart, const int* wid, const int* nb) {
    const float* wqkv = wset + OFF_QKV;
    const float* wo   = wset + OFF_WO;
    const float* w1   = wset + OFF_W1;
    const float* w2   = wset + OFF_W2;
    gemm_as<128, 128, 128, 2, 2, false, true>
        <<<dim3(SQ / 128, BT / 128, 1), 128>>>(
        xin, wqkv, qkv, cF, cF, SQ, SQ, 1.f);
    attn_fused<<<dim3(NQT, cB * cH), 128>>>(qkv, ao, colpart, wid, nb, mode);
    gemm_as<128, 128, 128, 2, 2, false, false>
        <<<dim3(cF / 128, BT / 128, 1), 128>>>(
        ao, wo, pj, cF, cF, cF, cF, 1.f);
    colreduce<<<(BT + 255) / 256, 256>>>(colpart, score, 1.0f / (cH * cT));
    ln_kernel<<<BT, 128>>>(xin, pj, y, 1);
    gemm_as<128, 128, 128, 2, 2, true, true>
        <<<dim3(cFF / 128, BT / 128, 1), 128>>>(
        y, w1, h, cF, cF, cFF, cFF, 1.f);
    gemm_as<128, 128, 128, 2, 2, false, false>
        <<<dim3(cF / 128, BT / 128, 1), 128>>>(
        h, w2, pj, cFF, cFF, cF, cF, 1.f);
    ln_kernel<<<BT, 128>>>(y, pj, yout, 0);
}

extern "C" void kernel_launch(void* const* d_in, const int* in_sizes, int n_in,
                              void* d_out, int out_size) {
    (void)in_sizes; (void)n_in; (void)out_size;
    const float* x   = (const float*)d_in[0];
    const float* hs  = (const float*)d_in[1];
    const float* msk = (const float*)d_in[2];

    float* out      = (float*)d_out;
    float* out_thr  = out + (long)BT * cF;
    float* out_attn = out_thr + cB;

    float *xl, *qkv, *ao, *pj, *y, *h, *lx, *gy, *pre, *ls, *h2, *wise, *cp, *wt;
    int *wid, *nb, *ws;
    cudaGetSymbolAddress((void**)&xl,   g_xl);
    cudaGetSymbolAddress((void**)&qkv,  g_qkv);
    cudaGetSymbolAddress((void**)&ao,   g_ao);
    cudaGetSymbolAddress((void**)&pj,   g_pj);
    cudaGetSymbolAddress((void**)&y,    g_y);
    cudaGetSymbolAddress((void**)&h,    g_h);
    cudaGetSymbolAddress((void**)&lx,   g_lx);
    cudaGetSymbolAddress((void**)&gy,   g_gy);
    cudaGetSymbolAddress((void**)&pre,  g_pre);
    cudaGetSymbolAddress((void**)&ls,   g_ls);
    cudaGetSymbolAddress((void**)&h2,   g_h2);
    cudaGetSymbolAddress((void**)&wise, g_wise);
    cudaGetSymbolAddress((void**)&cp,   g_cp);
    cudaGetSymbolAddress((void**)&wt,   g_wt);
    cudaGetSymbolAddress((void**)&wid,  g_wid);
    cudaGetSymbolAddress((void**)&nb,   g_nb);
    cudaGetSymbolAddress((void**)&ws,   g_ws);

    WSrc wsrc;
    for (int j = 0; j < 12; j++) wsrc.p[j] = (const float*)d_in[3 + j];
    cvtw_all<<<dim3((cF * cFF + 255) / 256, 12), 256>>>(wsrc, wt);

    masks_kernel<<<cB, 256>>>(hs, msk, out_thr, wid, nb, ws, wise);
    ln_kernel<<<BT, 128>>>(x, nullptr, xl, 1);
    run_transformer(xl, wt, lx, ls, /*mode=*/0,
                    qkv, ao, pj, y, h, cp, wid, nb);
    scale_kernel<<<BT, 128>>>(lx, wise);
    pre_kernel<<<dim3(cT, cB), 128>>>(lx, ls, nb, ws, pre);
    ln_kernel<<<BT, 128>>>(pre, nullptr, xl, 1);
    run_transformer(xl, wt + WSET, gy, h2, /*mode=*/1,
                    qkv, ao, pj, y, h, cp, wid, nb);
    final_data<<<BT, 128>>>(lx, gy, wid, out);
    final_attn<<<cB, 256>>>(ls, h2, wid, out_attn);
}

// round 14
// speedup vs baseline: 1.0506x; 1.0506x over previous
#include <cuda_runtime.h>
#include <math.h>

// ---------------------------------------------------------------------------
// DWFormerBlock round 14: R12 GEMM pipeline (issue-before-wait, known good)
// + warp-parity k8 stagger (anti-phase LDS/MMA between co-resident warps);
// attention keeps R13's active-list + ping-pong phase 1.
// ---------------------------------------------------------------------------

constexpr int cB  = 16;
constexpr int cT  = 768;
constexpr int cF  = 512;
constexpr int cFF = 2048;
constexpr int cH  = 8;
constexpr int cDH = 64;
constexpr int BT  = cB * cT;       // 12288
constexpr float NEGVAL = -1e30f;

constexpr int QT   = 64;
constexpr int KBL  = 64;
constexpr int NQT  = cT / QT;      // 12
constexpr int NBLK = cT / KBL;     // 12
constexpr int SQ   = 3 * cF;       // 1536

constexpr long OFF_QKV = 0;
constexpr long OFF_WO  = (long)cF * SQ;
constexpr long OFF_W1  = OFF_WO + (long)cF * cF;
constexpr long OFF_W2  = OFF_W1 + (long)cF * cFF;
constexpr long WSET    = OFF_W2 + (long)cFF * cF;

// ------------------------------- scratch -----------------------------------
__device__ float g_xl  [BT * cF];
__device__ float g_qkv [(long)BT * SQ];
__device__ float g_ao  [BT * cF];
__device__ float g_pj  [BT * cF];
__device__ float g_y   [BT * cF];
__device__ float g_h   [BT * cFF];
__device__ float g_lx  [BT * cF];
__device__ float g_gy  [BT * cF];
__device__ float g_pre [BT * cF];
__device__ float g_ls  [BT];
__device__ float g_h2  [BT];
__device__ float g_wise[BT];
__device__ float g_cp  [(long)cB * cH * NQT * cT];
__device__ float g_wt  [2 * WSET];
__device__ int   g_wid [BT];
__device__ int   g_nb  [cB];
__device__ int   g_ws  [cB * (cT + 1)];

// --------------------------- small helpers ---------------------------------
__device__ __forceinline__ unsigned tf32r(float f) {
    unsigned u;
    asm("cvt.rna.tf32.f32 %0, %1;" : "=r"(u) : "f"(f));
    return u;
}
__device__ __forceinline__ float tf32f(float f) {
    return __uint_as_float(tf32r(f));
}

__device__ __forceinline__ void mma_tf32(float& d0, float& d1, float& d2, float& d3,
                                         unsigned a0, unsigned a1, unsigned a2, unsigned a3,
                                         unsigned b0, unsigned b1) {
    asm volatile(
        "mma.sync.aligned.m16n8k8.row.col.f32.tf32.tf32.f32 "
        "{%0,%1,%2,%3}, {%4,%5,%6,%7}, {%8,%9}, {%0,%1,%2,%3};"
        : "+f"(d0), "+f"(d1), "+f"(d2), "+f"(d3)
        : "r"(a0), "r"(a1), "r"(a2), "r"(a3), "r"(b0), "r"(b1));
}

__device__ __forceinline__ void cpasync16(void* sdst, const void* gsrc) {
    unsigned s = (unsigned)__cvta_generic_to_shared(sdst);
    asm volatile("cp.async.cg.shared.global [%0], [%1], 16;" :: "r"(s), "l"(gsrc));
}
__device__ __forceinline__ void cp_commit() {
    asm volatile("cp.async.commit_group;");
}
template <int N>
__device__ __forceinline__ void cp_wait() {
    asm volatile("cp.async.wait_group %0;" :: "n"(N));
}

__device__ __forceinline__ float redMax256(float v) {
    __shared__ float sm[8];
#pragma unroll
    for (int o = 16; o > 0; o >>= 1) v = fmaxf(v, __shfl_xor_sync(0xffffffffu, v, o));
    if ((threadIdx.x & 31) == 0) sm[threadIdx.x >> 5] = v;
    __syncthreads();
    if (threadIdx.x == 0) {
        float m = sm[0];
#pragma unroll
        for (int i = 1; i < 8; i++) m = fmaxf(m, sm[i]);
        sm[0] = m;
    }
    __syncthreads();
    float r = sm[0];
    __syncthreads();
    return r;
}

__device__ __forceinline__ float redSum256(float v) {
    __shared__ float sm[8];
#pragma unroll
    for (int o = 16; o > 0; o >>= 1) v += __shfl_xor_sync(0xffffffffu, v, o);
    if ((threadIdx.x & 31) == 0) sm[threadIdx.x >> 5] = v;
    __syncthreads();
    if (threadIdx.x == 0) {
        float s = 0.f;
#pragma unroll
        for (int i = 0; i < 8; i++) s += sm[i];
        sm[0] = s;
    }
    __syncthreads();
    float r = sm[0];
    __syncthreads();
    return r;
}

// ----------------------- packed weight tf32 conversion ---------------------
struct WSrc { const float* p[12]; };

__global__ void cvtw_all(WSrc ws, float* __restrict__ dst) {
    int j = blockIdx.y;
    int i = blockIdx.x * 256 + threadIdx.x;
    int t = j / 6, jj = j % 6;
    long tb = (long)t * WSET;
    const float* src = ws.p[j];
    if (jj < 3) {
        if (i < cF * cF) {
            int r = i >> 9, c = i & 511;
            dst[tb + OFF_QKV + (long)r * SQ + jj * cF + c] = tf32f(src[i]);
        }
    } else if (jj == 3) {
        if (i < cF * cF)  dst[tb + OFF_WO + i] = tf32f(src[i]);
    } else if (jj == 4) {
        if (i < cF * cFF) dst[tb + OFF_W1 + i] = tf32f(src[i]);
    } else {
        if (i < cFF * cF) dst[tb + OFF_W2 + i] = tf32f(src[i]);
    }
}

// ------------------------------- masks kernel ------------------------------
__global__ void masks_kernel(const float* __restrict__ hs, const float* __restrict__ msk,
                             float* __restrict__ thr_out, int* __restrict__ wid,
                             int* __restrict__ nbarr, int* __restrict__ ws,
                             float* __restrict__ wise) {
    int b = blockIdx.x, tid = threadIdx.x;
    __shared__ float ss[1024];
    __shared__ int a1[cT];
    __shared__ int x3[cT];
    __shared__ float red[256];
    __shared__ float sthr;

    for (int i = tid; i < 1024; i += 256)
        ss[i] = (i < cT) ? hs[b * cT + i] : 3.402823466e38f;
    __syncthreads();

    for (int k2 = 2; k2 <= 1024; k2 <<= 1) {
        for (int j = k2 >> 1; j > 0; j >>= 1) {
            for (int i = tid; i < 1024; i += 256) {
                int l = i ^ j;
                if (l > i) {
                    float a = ss[i], c = ss[l];
                    bool up = ((i & k2) == 0);
                    if ((a > c) == up) { ss[i] = c; ss[l] = a; }
                }
            }
            __syncthreads();
        }
    }

    float m1 = 0.f;
    for (int i = tid; i < cT; i += 256) m1 += 1.0f - msk[b * cT + i];
    red[tid] = m1; __syncthreads();
    for (int s = 128; s > 0; s >>= 1) {
        if (tid < s) red[tid] += red[tid + s];
        __syncthreads();
    }
    if (tid == 0) {
        float mm = red[0];
        int med = (int)(mm * 0.5f + (float)cT - mm);
        if (med > cT - 1) med = cT - 1;
        if (med < 0) med = 0;
        sthr = ss[med];
        thr_out[b] = sthr;
    }
    __syncthreads();
    float thr = sthr;

    for (int i = tid; i < cT; i += 256) {
        int keep = (hs[b * cT + i] >= thr) ? 1 : 0;
        a1[i] = keep;
        wise[b * cT + i] = keep ? 1.0f : 0.85f;
    }
    __syncthreads();
    for (int i = tid; i < cT; i += 256) {
        int x2 = (i < cT - 1) ? a1[i + 1] : (1 - a1[cT - 1]);
        x3[i] = (x2 != a1[i]) ? 1 : 0;
    }
    __syncthreads();
    if (tid == 0) {
        int c = 0;
        ws[b * (cT + 1)] = 0;
        int prev = 0;
        for (int t = 0; t < cT; t++) {
            int xt = x3[t];
            int xm = (xt == 1 && prev == 1) ? 0 : xt;
            if (t == cT - 1) xm = 1;
            prev = xt;
            wid[b * cT + t] = c;
            if (xm) { c++; ws[b * (cT + 1) + c] = t + 1; }
        }
        nbarr[b] = c;
    }
}

// ------------------------------ layernorm ----------------------------------
__global__ void ln_kernel(const float* __restrict__ X, const float* __restrict__ R,
                          float* __restrict__ Y, int rnd) {
    long row = blockIdx.x;
    float4 v = ((const float4*)(X + row * cF))[threadIdx.x];
    if (R) {
        float4 r = ((const float4*)(R + row * cF))[threadIdx.x];
        v.x += r.x; v.y += r.y; v.z += r.z; v.w += r.w;
    }
    float s = v.x + v.y + v.z + v.w;
    float q = v.x * v.x + v.y * v.y + v.z * v.z + v.w * v.w;
    __shared__ float rs[4], rq[4];
#pragma unroll
    for (int o = 16; o > 0; o >>= 1) {
        s += __shfl_down_sync(0xffffffffu, s, o);
        q += __shfl_down_sync(0xffffffffu, q, o);
    }
    int w = threadIdx.x >> 5;
    if ((threadIdx.x & 31) == 0) { rs[w] = s; rq[w] = q; }
    __syncthreads();
    s = rs[0] + rs[1] + rs[2] + rs[3];
    q = rq[0] + rq[1] + rq[2] + rq[3];
    float mean = s * (1.0f / cF);
    float var  = q * (1.0f / cF) - mean * mean;
    float inv  = rsqrtf(var + 1e-5f);
    float4 o4 = make_float4((v.x - mean) * inv, (v.y - mean) * inv,
                            (v.z - mean) * inv, (v.w - mean) * inv);
    if (rnd) {
        o4.x = tf32f(o4.x); o4.y = tf32f(o4.y);
        o4.z = tf32f(o4.z); o4.w = tf32f(o4.w);
    }
    ((float4*)(Y + row * cF))[threadIdx.x] = o4;
}

// --------------------------- TF32 tensor GEMM (cp.async) -------------------
// R12 pipeline (issue next stage, then wait<1>) + warp-parity k8 stagger.
template <int BM, int BN, int NT, int WM, int WN, bool RELU, bool ROUND>
__global__ void __launch_bounds__(NT, 2)
gemm_as(const float* __restrict__ A, const float* __restrict__ Bm, float* __restrict__ C,
        int K, int lda, int ldb, int ldc, float alpha) {
    constexpr int BK  = 16;
    constexpr int BKP = BK + 4;
    constexpr int BNP = BN + 8;
    constexpr int MT  = BM / WM / 16;
    constexpr int NTT = BN / WN / 8;
    constexpr int AI  = BM * BK / 4 / NT;
    constexpr int BI  = BN * BK / 4 / NT;
    static_assert(AI * NT * 4 == BM * BK, "A tile");
    static_assert(BI * NT * 4 == BN * BK, "B tile");

    __shared__ float As[2][BM][BKP];
    __shared__ float Bs[2][BK][BNP];

    int tid  = threadIdx.x;
    int wid  = tid >> 5, lane = tid & 31;
    int g    = lane >> 2, c = lane & 3;
    int wm0  = (wid % WM) * (BM / WM);
    int wn0  = (wid / WM) * (BN / WN);
    int m0   = blockIdx.y * BM, n0 = blockIdx.x * BN;
    int kflip = (wid & 1) ? (BK - 8) : 0;   // anti-phase k8 order per warp

    float acc[MT][NTT][4] = {};

    auto issue = [&](int s, int k0) {
#pragma unroll
        for (int i = 0; i < AI; i++) {
            int e = tid + i * NT;
            int m = e >> 2, kq = (e & 3) << 2;
            cpasync16(&As[s][m][kq], A + (long)(m0 + m) * lda + k0 + kq);
        }
#pragma unroll
        for (int i = 0; i < BI; i++) {
            int e = tid + i * NT;
            int kk = e / (BN / 4), nq = (e % (BN / 4)) * 4;
            cpasync16(&Bs[s][kk][nq], Bm + (long)(k0 + kk) * ldb + n0 + nq);
        }
        cp_commit();
    };

    int KT = K / BK;
    issue(0, 0);

    for (int it = 0; it < KT; it++) {
        if (it + 1 < KT) issue((it + 1) & 1, (it + 1) * BK);
        else             cp_commit();
        cp_wait<1>();
        __syncthreads();

        int buf = it & 1;
#pragma unroll
        for (int kx = 0; kx < BK; kx += 8) {
            int kk = kx ^ kflip;
            unsigned af[MT][4];
#pragma unroll
            for (int i = 0; i < MT; i++) {
                int r0 = wm0 + i * 16 + g;
                af[i][0] = __float_as_uint(As[buf][r0][kk + c]);
                af[i][1] = __float_as_uint(As[buf][r0 + 8][kk + c]);
                af[i][2] = __float_as_uint(As[buf][r0][kk + c + 4]);
                af[i][3] = __float_as_uint(As[buf][r0 + 8][kk + c + 4]);
            }
            unsigned bf[NTT][2];
#pragma unroll
            for (int j = 0; j < NTT; j++) {
                int n = wn0 + j * 8 + g;
                bf[j][0] = __float_as_uint(Bs[buf][kk + c][n]);
                bf[j][1] = __float_as_uint(Bs[buf][kk + c + 4][n]);
            }
#pragma unroll
            for (int i = 0; i < MT; i++)
#pragma unroll
                for (int j = 0; j < NTT; j++)
                    mma_tf32(acc[i][j][0], acc[i][j][1], acc[i][j][2], acc[i][j][3],
                             af[i][0], af[i][1], af[i][2], af[i][3],
                             bf[j][0], bf[j][1]);
        }
        __syncthreads();
    }

#pragma unroll
    for (int i = 0; i < MT; i++) {
#pragma unroll
        for (int j = 0; j < NTT; j++) {
            int row0 = m0 + wm0 + i * 16 + g;
            int col  = n0 + wn0 + j * 8 + c * 2;
            float vals[4];
#pragma unroll
            for (int t = 0; t < 4; t++) {
                float vv = acc[i][j][t] * alpha;
                if (RELU)  vv = fmaxf(vv, 0.f);
                if (ROUND) vv = tf32f(vv);
                vals[t] = vv;
            }
            *(float2*)(C + (long)row0 * ldc + col)       = make_float2(vals[0], vals[1]);
            *(float2*)(C + (long)(row0 + 8) * ldc + col) = make_float2(vals[2], vals[3]);
        }
    }
}

// ------------------------ fused attention kernel ---------------------------
// Active-block list + ping-pong K buffers in phase 1 (from R13); phase 2 as
// in R12 with per-block skip.
__global__ void __launch_bounds__(128, 2)
attn_fused(const float* __restrict__ QKV, float* __restrict__ AO,
           float* __restrict__ colpart,
           const int* __restrict__ widp, const int* __restrict__ nbp, int mode) {
    __shared__ float pool[8960];
    __shared__ float red[2][QT];
    __shared__ float sm_t[QT];
    __shared__ int   wq_s[QT], wk_s[2][KBL];
    __shared__ int   act[NBLK], actflag[NBLK], s_cnt;

    float (*B0)[68] = (float(*)[68])pool;
    float (*B1)[68] = (float(*)[68])(pool + 4352);
    float (*Vs)[72] = (float(*)[72])(pool + 4352);

    int qt = blockIdx.x, bh = blockIdx.y;
    int b = bh >> 3;
    int tid = threadIdx.x, wid = tid >> 5, lane = tid & 31;
    int g = lane >> 2, c = lane & 3;
    int wq0 = (wid & 1) * 32;
    int wk0 = (wid >> 1) * 32;
    int kgrp = wid >> 1;
    int q0 = qt * QT;
    long base = (long)b * cT * SQ + (bh & 7) * cDH;
    const float* Qp = QKV + base;
    const float* Kp = QKV + base + cF;
    const float* Vp = QKV + base + 2 * cF;
    int nbv = (mode == 1) ? __ldg(&nbp[b]) : 0;

    // ---- stage Q tile; thread 0 builds active-block list ----
#pragma unroll
    for (int i = 0; i < 8; i++) {
        int e = tid + i * 128;
        int r = e >> 4, cq = (e & 15) << 2;
        cpasync16(&B0[r][cq], Qp + (long)(q0 + r) * SQ + cq);
    }
    cp_commit();
    if (mode == 0 && tid < QT) wq_s[tid] = __ldg(&widp[b * cT + q0 + tid]);
    if (tid == 0) {
        int cnt = 0;
        if (mode == 0) {
            int wq_lo = __ldg(&widp[b * cT + q0]);
            int wq_hi = __ldg(&widp[b * cT + q0 + QT - 1]);
            for (int kb = 0; kb < NBLK; kb++) {
                int klo = __ldg(&widp[b * cT + kb * KBL]);
                int khi = __ldg(&widp[b * cT + kb * KBL + KBL - 1]);
                int a = (klo <= wq_hi) && (khi >= wq_lo);
                actflag[kb] = a;
                if (a) act[cnt++] = kb;
            }
        } else {
            for (int kb = 0; kb < NBLK; kb++) {
                int a = (kb * KBL < nbv);
                actflag[kb] = a;
                if (a) act[cnt++] = kb;
            }
        }
        s_cnt = cnt;
    }
    cp_wait<0>();
    __syncthreads();

    unsigned aq[2][8][4];
#pragma unroll
    for (int i = 0; i < 2; i++) {
        int r0 = wq0 + i * 16 + g;
#pragma unroll
        for (int kk = 0; kk < 8; kk++) {
            aq[i][kk][0] = __float_as_uint(B0[r0][kk * 8 + c]);
            aq[i][kk][1] = __float_as_uint(B0[r0 + 8][kk * 8 + c]);
            aq[i][kk][2] = __float_as_uint(B0[r0][kk * 8 + c + 4]);
            aq[i][kk][3] = __float_as_uint(B0[r0 + 8][kk * 8 + c + 4]);
        }
    }
    int cnt = s_cnt;
    __syncthreads();          // all warps done reading Q from B0

    auto issueK = [&](int s, int kb) {
        float (*dst)[68] = s ? B1 : B0;
#pragma unroll
        for (int i = 0; i < 8; i++) {
            int e = tid + i * 128;
            int r = e >> 4, cq = (e & 15) << 2;
            cpasync16(&dst[r][cq], Kp + (long)(kb * KBL + r) * SQ + cq);
        }
        cp_commit();
        if (mode == 0 && tid < KBL)
            wk_s[s][tid] = __ldg(&widp[b * cT + kb * KBL + tid]);
    };

    // ---- phase 1: row denominators over active blocks ----
    float rsum[4] = {};
    if (cnt > 0) {
        issueK(0, act[0]);
        for (int ii = 0; ii < cnt; ii++) {
            if (ii + 1 < cnt) issueK((ii + 1) & 1, act[ii + 1]);
            else              cp_commit();
            cp_wait<1>();
            __syncthreads();

            int kb = act[ii];
            float (*Kb)[68] = (ii & 1) ? B1 : B0;
            const int* wk = wk_s[ii & 1];
            float sacc[2][4][4] = {};
#pragma unroll
            for (int kk = 0; kk < 8; kk++) {
                unsigned bf[4][2];
#pragma unroll
                for (int j = 0; j < 4; j++) {
                    int n = wk0 + j * 8 + g;
                    bf[j][0] = __float_as_uint(Kb[n][kk * 8 + c]);
                    bf[j][1] = __float_as_uint(Kb[n][kk * 8 + c + 4]);
                }
#pragma unroll
                for (int i = 0; i < 2; i++)
#pragma unroll
                    for (int j = 0; j < 4; j++)
                        mma_tf32(sacc[i][j][0], sacc[i][j][1], sacc[i][j][2], sacc[i][j][3],
                                 aq[i][kk][0], aq[i][kk][1], aq[i][kk][2], aq[i][kk][3],
                                 bf[j][0], bf[j][1]);
            }
#pragma unroll
            for (int i = 0; i < 2; i++)
#pragma unroll
                for (int j = 0; j < 4; j++)
#pragma unroll
                    for (int e = 0; e < 4; e++) {
                        float s = sacc[i][j][e] * 0.125f;
                        int qr = wq0 + i * 16 + g + ((e >> 1) ? 8 : 0);
                        int kc = wk0 + j * 8 + 2 * c + (e & 1);
                        bool msk = (mode == 0) ? (wk[kc] != wq_s[qr])
                                               : (kb * KBL + kc >= nbv);
                        int ri = i * 2 + (e >> 1);
                        if (!msk) rsum[ri] += __expf(s);
                    }
            __syncthreads();
        }
    }
#pragma unroll
    for (int r = 0; r < 4; r++) {
        rsum[r] += __shfl_xor_sync(0xffffffffu, rsum[r], 1);
        rsum[r] += __shfl_xor_sync(0xffffffffu, rsum[r], 2);
    }
    if (c == 0) {
#pragma unroll
        for (int r = 0; r < 4; r++)
            red[kgrp][wq0 + (r >> 1) * 16 + g + ((r & 1) ? 8 : 0)] = rsum[r];
    }
    __syncthreads();
    if (tid < QT) sm_t[tid] = 1.0f / (red[0][tid] + red[1][tid]);
    __syncthreads();

    // ---- phase 2: A, colsums, out (active blocks only) ----
    float oacc[2][4][4] = {};
    for (int kb = 0; kb < NBLK; kb++) {
        if (!actflag[kb]) {
            if (tid < KBL)
                colpart[((long)bh * NQT + qt) * cT + kb * KBL + tid] = 0.f;
            continue;
        }
#pragma unroll
        for (int i = 0; i < 8; i++) {
            int e = tid + i * 128;
            int r = e >> 4, cq = (e & 15) << 2;
            cpasync16(&B0[r][cq], Kp + (long)(kb * KBL + r) * SQ + cq);
            cpasync16(&Vs[r][cq], Vp + (long)(kb * KBL + r) * SQ + cq);
        }
        cp_commit();
        if (mode == 0 && tid < KBL) wk_s[0][tid] = __ldg(&widp[b * cT + kb * KBL + tid]);
        cp_wait<0>();
        __syncthreads();

        float sacc[2][4][4] = {};
#pragma unroll
        for (int kk = 0; kk < 8; kk++) {
            unsigned bf[4][2];
#pragma unroll
            for (int j = 0; j < 4; j++) {
                int n = wk0 + j * 8 + g;
                bf[j][0] = __float_as_uint(B0[n][kk * 8 + c]);
                bf[j][1] = __float_as_uint(B0[n][kk * 8 + c + 4]);
            }
#pragma unroll
            for (int i = 0; i < 2; i++)
#pragma unroll
                for (int j = 0; j < 4; j++)
                    mma_tf32(sacc[i][j][0], sacc[i][j][1], sacc[i][j][2], sacc[i][j][3],
                             aq[i][kk][0], aq[i][kk][1], aq[i][kk][2], aq[i][kk][3],
                             bf[j][0], bf[j][1]);
        }
        float idr[4];
#pragma unroll
        for (int r = 0; r < 4; r++)
            idr[r] = sm_t[wq0 + (r >> 1) * 16 + g + ((r & 1) ? 8 : 0)];
#pragma unroll
        for (int i = 0; i < 2; i++)
#pragma unroll
            for (int j = 0; j < 4; j++)
#pragma unroll
                for (int e = 0; e < 4; e++) {
                    float s = sacc[i][j][e] * 0.125f;
                    int qr = wq0 + i * 16 + g + ((e >> 1) ? 8 : 0);
                    int kc = wk0 + j * 8 + 2 * c + (e & 1);
                    bool msk = (mode == 0) ? (wk_s[0][kc] != wq_s[qr])
                                           : (kb * KBL + kc >= nbv);
                    int ri = i * 2 + (e >> 1);
                    float ev = msk ? 0.f : __expf(s);
                    sacc[i][j][e] = tf32f(ev * idr[ri]);
                }
        __syncthreads();
#pragma unroll
        for (int i = 0; i < 2; i++)
#pragma unroll
            for (int j = 0; j < 4; j++) {
                int qr = wq0 + i * 16 + g;
                int kc = wk0 + j * 8 + 2 * c;
                *(float2*)&B0[qr][kc]     = make_float2(sacc[i][j][0], sacc[i][j][1]);
                *(float2*)&B0[qr + 8][kc] = make_float2(sacc[i][j][2], sacc[i][j][3]);
            }
        __syncthreads();
        if (tid < KBL) {
            float cs = 0.f;
#pragma unroll 8
            for (int qq = 0; qq < QT; qq++) cs += B0[qq][tid];
            colpart[((long)bh * NQT + qt) * cT + kb * KBL + tid] = cs;
        }
#pragma unroll
        for (int kk = 0; kk < 8; kk++) {
            unsigned af[2][4], bf[4][2];
#pragma unroll
            for (int i = 0; i < 2; i++) {
                int r0 = wq0 + i * 16 + g;
                af[i][0] = __float_as_uint(B0[r0][kk * 8 + c]);
                af[i][1] = __float_as_uint(B0[r0 + 8][kk * 8 + c]);
                af[i][2] = __float_as_uint(B0[r0][kk * 8 + c + 4]);
                af[i][3] = __float_as_uint(B0[r0 + 8][kk * 8 + c + 4]);
            }
#pragma unroll
            for (int j = 0; j < 4; j++) {
                int n = wk0 + j * 8 + g;
                bf[j][0] = __float_as_uint(Vs[kk * 8 + c][n]);
                bf[j][1] = __float_as_uint(Vs[kk * 8 + c + 4][n]);
            }
#pragma unroll
            for (int i = 0; i < 2; i++)
#pragma unroll
                for (int j = 0; j < 4; j++)
                    mma_tf32(oacc[i][j][0], oacc[i][j][1], oacc[i][j][2], oacc[i][j][3],
                             af[i][0], af[i][1], af[i][2], af[i][3],
                             bf[j][0], bf[j][1]);
        }
        __syncthreads();
    }

#pragma unroll
    for (int i = 0; i < 2; i++)
#pragma unroll
        for (int j = 0; j < 4; j++) {
            int qg = q0 + wq0 + i * 16 + g;
            int dh = wk0 + j * 8 + 2 * c;
            long o0 = ((long)b * cT + qg) * cF + (bh & 7) * cDH + dh;
            *(float2*)&AO[o0] =
                make_float2(tf32f(oacc[i][j][0]), tf32f(oacc[i][j][1]));
            *(float2*)&AO[o0 + 8L * cF] =
                make_float2(tf32f(oacc[i][j][2]), tf32f(oacc[i][j][3]));
        }
}

// -------------------- colsum partial reduction -> score --------------------
__global__ void colreduce(const float* __restrict__ cp, float* __restrict__ outv,
                          float scale) {
    int t = blockIdx.x * 256 + threadIdx.x;
    if (t >= BT) return;
    int b = t / cT, k = t - b * cT;
    float s = 0.f;
    for (int h = 0; h < cH; h++)
#pragma unroll
        for (int q = 0; q < NQT; q++)
            s += cp[(((long)(b * cH + h)) * NQT + q) * cT + k];
    outv[t] = s * scale;
}

// ------------------- window aggregation: pre[b,w,:] ------------------------
__global__ void pre_kernel(const float* __restrict__ lx, const float* __restrict__ ls,
                           const int* __restrict__ nbarr, const int* __restrict__ ws,
                           float* __restrict__ pre) {
    int b = blockIdx.y, w = blockIdx.x, tid = threadIdx.x;
    float4 acc = make_float4(0.f, 0.f, 0.f, 0.f);
    if (w < nbarr[b]) {
        int s = ws[b * (cT + 1) + w];
        int e = ws[b * (cT + 1) + w + 1];
        for (int t = s; t < e; t++) {
            float sc = __ldg(&ls[b * cT + t]);
            float4 v = ((const float4*)(lx + ((long)b * cT + t) * cF))[tid];
            acc.x = fmaf(v.x, sc, acc.x); acc.y = fmaf(v.y, sc, acc.y);
            acc.z = fmaf(v.z, sc, acc.z); acc.w = fmaf(v.w, sc, acc.w);
        }
    }
    ((float4*)(pre + ((long)b * cT + w) * cF))[tid] = acc;
}

// --------------------------- misc elementwise ------------------------------
__global__ void scale_kernel(float* __restrict__ yx, const float* __restrict__ wise) {
    long row = blockIdx.x;
    float sc = wise[row];
    float4 v = ((const float4*)(yx + row * cF))[threadIdx.x];
    v.x *= sc; v.y *= sc; v.z *= sc; v.w *= sc;
    ((float4*)(yx + row * cF))[threadIdx.x] = v;
}

__global__ void final_data(const float* __restrict__ lx, const float* __restrict__ gy,
                           const int* __restrict__ wid, float* __restrict__ outd) {
    long i = blockIdx.x;
    int b = (int)(i / cT);
    int w = wid[i];
    float4 a = ((const float4*)(lx + i * cF))[threadIdx.x];
    float4 g = ((const float4*)(gy + ((long)b * cT + w) * cF))[threadIdx.x];
    a.x += g.x; a.y += g.y; a.z += g.z; a.w += g.w;
    ((float4*)(outd + i * cF))[threadIdx.x] = a;
}

__global__ void final_attn(const float* __restrict__ ls, const float* __restrict__ h2,
                           const int* __restrict__ wid, float* __restrict__ outa) {
    int b = blockIdx.x, tid = threadIdx.x;
    float xv[3];
#pragma unroll
    for (int i = 0; i < 3; i++) {
        int t = tid + i * 256;
        xv[i] = ls[b * cT + t] * h2[b * cT + wid[b * cT + t]];
    }
    float mx = redMax256(fmaxf(fmaxf(xv[0], xv[1]), xv[2]));
    float e[3];
    float s = 0.f;
#pragma unroll
    for (int i = 0; i < 3; i++) { e[i] = expf(xv[i] - mx); s += e[i]; }
    s = redSum256(s);
    float inv = 1.0f / s;
#pragma unroll
    for (int i = 0; i < 3; i++) outa[b * cT + tid + i * 256] = e[i] * inv;
}

// ------------------------------ host side ----------------------------------
static void run_transformer(const float* xin, const float* wset,
                            float* yout, float* score, int mode,
                            float* qkv, float* ao, float* pj, float* y, float* h,
                            float* colpart, const int* wid, const int* nb) {
    const float* wqkv = wset + OFF_QKV;
    const float* wo   = wset + OFF_WO;
    const float* w1   = wset + OFF_W1;
    const float* w2   = wset + OFF_W2;
    gemm_as<128, 128, 128, 2, 2, false, true>
        <<<dim3(SQ / 128, BT / 128, 1), 128>>>(
        xin, wqkv, qkv, cF, cF, SQ, SQ, 1.f);
    attn_fused<<<dim3(NQT, cB * cH), 128>>>(qkv, ao, colpart, wid, nb, mode);
    gemm_as<128, 128, 128, 2, 2, false, false>
        <<<dim3(cF / 128, BT / 128, 1), 128>>>(
        ao, wo, pj, cF, cF, cF, cF, 1.f);
    colreduce<<<(BT + 255) / 256, 256>>>(colpart, score, 1.0f / (cH * cT));
    ln_kernel<<<BT, 128>>>(xin, pj, y, 1);
    gemm_as<128, 128, 128, 2, 2, true, true>
        <<<dim3(cFF / 128, BT / 128, 1), 128>>>(
        y, w1, h, cF, cF, cFF, cFF, 1.f);
    gemm_as<128, 128, 128, 2, 2, false, false>
        <<<dim3(cF / 128, BT / 128, 1), 128>>>(
        h, w2, pj, cFF, cFF, cF, cF, 1.f);
    ln_kernel<<<BT, 128>>>(y, pj, yout, 0);
}

extern "C" void kernel_launch(void* const* d_in, const int* in_sizes, int n_in,
                              void* d_out, int out_size) {
    (void)in_sizes; (void)n_in; (void)out_size;
    const float* x   = (const float*)d_in[0];
    const float* hs  = (const float*)d_in[1];
    const float* msk = (const float*)d_in[2];

    float* out      = (float*)d_out;
    float* out_thr  = out + (long)BT * cF;
    float* out_attn = out_thr + cB;

    float *xl, *qkv, *ao, *pj, *y, *h, *lx, *gy, *pre, *ls, *h2, *wise, *cp, *wt;
    int *wid, *nb, *ws;
    cudaGetSymbolAddress((void**)&xl,   g_xl);
    cudaGetSymbolAddress((void**)&qkv,  g_qkv);
    cudaGetSymbolAddress((void**)&ao,   g_ao);
    cudaGetSymbolAddress((void**)&pj,   g_pj);
    cudaGetSymbolAddress((void**)&y,    g_y);
    cudaGetSymbolAddress((void**)&h,    g_h);
    cudaGetSymbolAddress((void**)&lx,   g_lx);
    cudaGetSymbolAddress((void**)&gy,   g_gy);
    cudaGetSymbolAddress((void**)&pre,  g_pre);
    cudaGetSymbolAddress((void**)&ls,   g_ls);
    cudaGetSymbolAddress((void**)&h2,   g_h2);
    cudaGetSymbolAddress((void**)&wise, g_wise);
    cudaGetSymbolAddress((void**)&cp,   g_cp);
    cudaGetSymbolAddress((void**)&wt,   g_wt);
    cudaGetSymbolAddress((void**)&wid,  g_wid);
    cudaGetSymbolAddress((void**)&nb,   g_nb);
    cudaGetSymbolAddress((void**)&ws,   g_ws);

    WSrc wsrc;
    for (int j = 0; j < 12; j++) wsrc.p[j] = (const float*)d_in[3 + j];
    cvtw_all<<<dim3((cF * cFF + 255) / 256, 12), 256>>>(wsrc, wt);

    masks_kernel<<<cB, 256>>>(hs, msk, out_thr, wid, nb, ws, wise);
    ln_kernel<<<BT, 128>>>(x, nullptr, xl, 1);
    run_transformer(xl, wt, lx, ls, /*mode=*/0,
                    qkv, ao, pj, y, h, cp, wid, nb);
    scale_kernel<<<BT, 128>>>(lx, wise);
    pre_kernel<<<dim3(cT, cB), 128>>>(lx, ls, nb, ws, pre);
    ln_kernel<<<BT, 128>>>(pre, nullptr, xl, 1);
    run_transformer(xl, wt + WSET, gy, h2, /*mode=*/1,
                    qkv, ao, pj, y, h, cp, wid, nb);
    final_data<<<BT, 128>>>(lx, gy, wid, out);
    final_attn<<<cB, 256>>>(ls, h2, wid, out_attn);
}

// round 16
// speedup vs baseline: 1.6873x; 1.6060x over previous
#include <cuda_runtime.h>
#include <cuda_fp16.h>
#include <math.h>

// ---------------------------------------------------------------------------
// DWFormerBlock round 16 (= R15 resubmitted after infra failure, dead code
// removed): dense GEMMs on FP16 m16n8k16 tensor cores (fp32 accum; fp16
// mantissa == tf32 mantissa so the rel_err budget holds). Weights transposed
// + converted to [N][K] half once; GEMM activations stored half. Attention
// unchanged (tf32 on float qkv); ao output half.
// ---------------------------------------------------------------------------

constexpr int cB  = 16;
constexpr int cT  = 768;
constexpr int cF  = 512;
constexpr int cFF = 2048;
constexpr int cH  = 8;
constexpr int cDH = 64;
constexpr int BT  = cB * cT;       // 12288
constexpr float NEGVAL = -1e30f;

constexpr int QT   = 64;
constexpr int KBL  = 64;
constexpr int NQT  = cT / QT;      // 12
constexpr int NBLK = cT / KBL;     // 12
constexpr int SQ   = 3 * cF;       // 1536

constexpr long OFF_QKV = 0;                        // [1536][512] half
constexpr long OFF_WO  = (long)SQ * cF;            // [512][512]
constexpr long OFF_W1  = OFF_WO + (long)cF * cF;   // [2048][512]
constexpr long OFF_W2  = OFF_W1 + (long)cFF * cF;  // [512][2048]
constexpr long WSET    = OFF_W2 + (long)cF * cFF;

// ------------------------------- scratch -----------------------------------
__device__ __half g_xl [BT * cF];
__device__ float  g_qkv[(long)BT * SQ];
__device__ __half g_ao [BT * cF];
__device__ float  g_pj [BT * cF];
__device__ __half g_y  [BT * cF];
__device__ __half g_h  [BT * cFF];
__device__ float  g_lx [BT * cF];
__device__ float  g_gy [BT * cF];
__device__ float  g_pre[BT * cF];
__device__ float  g_xf [BT * cF];
__device__ float  g_ls [BT];
__device__ float  g_h2 [BT];
__device__ float  g_wise[BT];
__device__ float  g_cp [(long)cB * cH * NQT * cT];
__device__ __half g_wt [2 * WSET];
__device__ int    g_wid[BT];
__device__ int    g_nb [cB];
__device__ int    g_ws [cB * (cT + 1)];

// --------------------------- small helpers ---------------------------------
__device__ __forceinline__ unsigned tf32r(float f) {
    unsigned u;
    asm("cvt.rna.tf32.f32 %0, %1;" : "=r"(u) : "f"(f));
    return u;
}
__device__ __forceinline__ float tf32f(float f) {
    return __uint_as_float(tf32r(f));
}

__device__ __forceinline__ void mma_tf32(float& d0, float& d1, float& d2, float& d3,
                                         unsigned a0, unsigned a1, unsigned a2, unsigned a3,
                                         unsigned b0, unsigned b1) {
    asm volatile(
        "mma.sync.aligned.m16n8k8.row.col.f32.tf32.tf32.f32 "
        "{%0,%1,%2,%3}, {%4,%5,%6,%7}, {%8,%9}, {%0,%1,%2,%3};"
        : "+f"(d0), "+f"(d1), "+f"(d2), "+f"(d3)
        : "r"(a0), "r"(a1), "r"(a2), "r"(a3), "r"(b0), "r"(b1));
}

__device__ __forceinline__ void mma_f16(float& d0, float& d1, float& d2, float& d3,
                                        unsigned a0, unsigned a1, unsigned a2, unsigned a3,
                                        unsigned b0, unsigned b1) {
    asm volatile(
        "mma.sync.aligned.m16n8k16.row.col.f32.f16.f16.f32 "
        "{%0,%1,%2,%3}, {%4,%5,%6,%7}, {%8,%9}, {%0,%1,%2,%3};"
        : "+f"(d0), "+f"(d1), "+f"(d2), "+f"(d3)
        : "r"(a0), "r"(a1), "r"(a2), "r"(a3), "r"(b0), "r"(b1));
}

__device__ __forceinline__ void cpasync16(void* sdst, const void* gsrc) {
    unsigned s = (unsigned)__cvta_generic_to_shared(sdst);
    asm volatile("cp.async.cg.shared.global [%0], [%1], 16;" :: "r"(s), "l"(gsrc));
}
__device__ __forceinline__ void cp_commit() {
    asm volatile("cp.async.commit_group;");
}
template <int N>
__device__ __forceinline__ void cp_wait() {
    asm volatile("cp.async.wait_group %0;" :: "n"(N));
}

__device__ __forceinline__ float redMax256(float v) {
    __shared__ float sm[8];
#pragma unroll
    for (int o = 16; o > 0; o >>= 1) v = fmaxf(v, __shfl_xor_sync(0xffffffffu, v, o));
    if ((threadIdx.x & 31) == 0) sm[threadIdx.x >> 5] = v;
    __syncthreads();
    if (threadIdx.x == 0) {
        float m = sm[0];
#pragma unroll
        for (int i = 1; i < 8; i++) m = fmaxf(m, sm[i]);
        sm[0] = m;
    }
    __syncthreads();
    float r = sm[0];
    __syncthreads();
    return r;
}

__device__ __forceinline__ float redSum256(float v) {
    __shared__ float sm[8];
#pragma unroll
    for (int o = 16; o > 0; o >>= 1) v += __shfl_xor_sync(0xffffffffu, v, o);
    if ((threadIdx.x & 31) == 0) sm[threadIdx.x >> 5] = v;
    __syncthreads();
    if (threadIdx.x == 0) {
        float s = 0.f;
#pragma unroll
        for (int i = 0; i < 8; i++) s += sm[i];
        sm[0] = s;
    }
    __syncthreads();
    float r = sm[0];
    __syncthreads();
    return r;
}

// ---------------- weight transpose + fp16 convert (tiled) ------------------
__global__ void cvtT(const float* __restrict__ src, __half* __restrict__ dst,
                     int K, int N) {
    __shared__ float t[32][33];
    int k0 = blockIdx.x * 32, n0 = blockIdx.y * 32;
    int tx = threadIdx.x, ty = threadIdx.y;
#pragma unroll
    for (int i = 0; i < 4; i++)
        t[ty + 8 * i][tx] = src[(long)(k0 + ty + 8 * i) * N + n0 + tx];
    __syncthreads();
#pragma unroll
    for (int i = 0; i < 4; i++)
        dst[(long)(n0 + ty + 8 * i) * K + k0 + tx] =
            __float2half_rn(t[tx][ty + 8 * i]);
}

// ------------------------------- masks kernel ------------------------------
__global__ void masks_kernel(const float* __restrict__ hs, const float* __restrict__ msk,
                             float* __restrict__ thr_out, int* __restrict__ wid,
                             int* __restrict__ nbarr, int* __restrict__ ws,
                             float* __restrict__ wise) {
    int b = blockIdx.x, tid = threadIdx.x;
    __shared__ float ss[1024];
    __shared__ int a1[cT];
    __shared__ int x3[cT];
    __shared__ float red[256];
    __shared__ float sthr;

    for (int i = tid; i < 1024; i += 256)
        ss[i] = (i < cT) ? hs[b * cT + i] : 3.402823466e38f;
    __syncthreads();

    for (int k2 = 2; k2 <= 1024; k2 <<= 1) {
        for (int j = k2 >> 1; j > 0; j >>= 1) {
            for (int i = tid; i < 1024; i += 256) {
                int l = i ^ j;
                if (l > i) {
                    float a = ss[i], c = ss[l];
                    bool up = ((i & k2) == 0);
                    if ((a > c) == up) { ss[i] = c; ss[l] = a; }
                }
            }
            __syncthreads();
        }
    }

    float m1 = 0.f;
    for (int i = tid; i < cT; i += 256) m1 += 1.0f - msk[b * cT + i];
    red[tid] = m1; __syncthreads();
    for (int s = 128; s > 0; s >>= 1) {
        if (tid < s) red[tid] += red[tid + s];
        __syncthreads();
    }
    if (tid == 0) {
        float mm = red[0];
        int med = (int)(mm * 0.5f + (float)cT - mm);
        if (med > cT - 1) med = cT - 1;
        if (med < 0) med = 0;
        sthr = ss[med];
        thr_out[b] = sthr;
    }
    __syncthreads();
    float thr = sthr;

    for (int i = tid; i < cT; i += 256) {
        int keep = (hs[b * cT + i] >= thr) ? 1 : 0;
        a1[i] = keep;
        wise[b * cT + i] = keep ? 1.0f : 0.85f;
    }
    __syncthreads();
    for (int i = tid; i < cT; i += 256) {
        int x2 = (i < cT - 1) ? a1[i + 1] : (1 - a1[cT - 1]);
        x3[i] = (x2 != a1[i]) ? 1 : 0;
    }
    __syncthreads();
    if (tid == 0) {
        int c = 0;
        ws[b * (cT + 1)] = 0;
        int prev = 0;
        for (int t = 0; t < cT; t++) {
            int xt = x3[t];
            int xm = (xt == 1 && prev == 1) ? 0 : xt;
            if (t == cT - 1) xm = 1;
            prev = xt;
            wid[b * cT + t] = c;
            if (xm) { c++; ws[b * (cT + 1) + c] = t + 1; }
        }
        nbarr[b] = c;
    }
}

// ------------------------------ layernorm ----------------------------------
__device__ __forceinline__ float4 ln_core(float4 v) {
    float s = v.x + v.y + v.z + v.w;
    float q = v.x * v.x + v.y * v.y + v.z * v.z + v.w * v.w;
    __shared__ float rs[4], rq[4];
#pragma unroll
    for (int o = 16; o > 0; o >>= 1) {
        s += __shfl_down_sync(0xffffffffu, s, o);
        q += __shfl_down_sync(0xffffffffu, q, o);
    }
    int w = threadIdx.x >> 5;
    if ((threadIdx.x & 31) == 0) { rs[w] = s; rq[w] = q; }
    __syncthreads();
    s = rs[0] + rs[1] + rs[2] + rs[3];
    q = rq[0] + rq[1] + rq[2] + rq[3];
    float mean = s * (1.0f / cF);
    float var  = q * (1.0f / cF) - mean * mean;
    float inv  = rsqrtf(var + 1e-5f);
    return make_float4((v.x - mean) * inv, (v.y - mean) * inv,
                       (v.z - mean) * inv, (v.w - mean) * inv);
}

// Y(float, optional) and Yh(half twin, optional) = LN(X + R)
__global__ void ln_ff(const float* __restrict__ X, const float* __restrict__ R,
                      float* __restrict__ Y, __half* __restrict__ Yh) {
    long row = blockIdx.x;
    float4 v = ((const float4*)(X + row * cF))[threadIdx.x];
    if (R) {
        float4 r = ((const float4*)(R + row * cF))[threadIdx.x];
        v.x += r.x; v.y += r.y; v.z += r.z; v.w += r.w;
    }
    float4 o = ln_core(v);
    if (Y) ((float4*)(Y + row * cF))[threadIdx.x] = o;
    if (Yh) {
        __half2* oh = (__half2*)(Yh + row * cF);
        oh[2 * threadIdx.x]     = __floats2half2_rn(o.x, o.y);
        oh[2 * threadIdx.x + 1] = __floats2half2_rn(o.z, o.w);
    }
}

// --------------------------- FP16 tensor GEMM ------------------------------
// A [M][K] half row-major, Bt [N][K] half row-major. BK=32 halves,
// 2-stage cp.async (issue-before-wait), warp-parity k16 stagger.
// OUT: 0 = float, 1 = float tf32-rounded, 2 = half.
template <int BM, int BN, int NT, int WM, int WN, bool RELU, int OUT>
__global__ void __launch_bounds__(NT, 2)
gemm_h(const __half* __restrict__ A, const __half* __restrict__ Bt, void* Cv,
       int K, int lda, int ldb, int ldc, float alpha) {
    constexpr int BK   = 32;
    constexpr int BKPh = BK + 8;           // 40 halves = 80B rows (16B-aligned)
    constexpr int MT   = BM / WM / 16;
    constexpr int NTT  = BN / WN / 8;
    constexpr int AI   = BM * BK / 8 / NT;
    constexpr int BI   = BN * BK / 8 / NT;
    static_assert(AI * NT * 8 == BM * BK, "A tile");
    static_assert(BI * NT * 8 == BN * BK, "B tile");

    __shared__ __half As[2][BM][BKPh];
    __shared__ __half Bs[2][BN][BKPh];

    int tid  = threadIdx.x;
    int wid  = tid >> 5, lane = tid & 31;
    int g    = lane >> 2, c = lane & 3;
    int wm0  = (wid % WM) * (BM / WM);
    int wn0  = (wid / WM) * (BN / WN);
    int m0   = blockIdx.y * BM, n0 = blockIdx.x * BN;
    int kflip = (wid & 1) ? 16 : 0;

    float acc[MT][NTT][4] = {};

    auto issue = [&](int s, int k0) {
#pragma unroll
        for (int i = 0; i < AI; i++) {
            int e = tid + i * NT;
            int m = e >> 2, kq = (e & 3) << 3;
            cpasync16(&As[s][m][kq], A + (long)(m0 + m) * lda + k0 + kq);
        }
#pragma unroll
        for (int i = 0; i < BI; i++) {
            int e = tid + i * NT;
            int n = e >> 2, kq = (e & 3) << 3;
            cpasync16(&Bs[s][n][kq], Bt + (long)(n0 + n) * ldb + k0 + kq);
        }
        cp_commit();
    };

    int KT = K / BK;
    issue(0, 0);

    for (int it = 0; it < KT; it++) {
        if (it + 1 < KT) issue((it + 1) & 1, (it + 1) * BK);
        else             cp_commit();
        cp_wait<1>();
        __syncthreads();

        int buf = it & 1;
#pragma unroll
        for (int kx = 0; kx < BK; kx += 16) {
            int ks = kx ^ kflip;
            unsigned af[MT][4];
#pragma unroll
            for (int i = 0; i < MT; i++) {
                int r0 = wm0 + i * 16 + g;
                af[i][0] = *(const unsigned*)&As[buf][r0][ks + 2 * c];
                af[i][1] = *(const unsigned*)&As[buf][r0 + 8][ks + 2 * c];
                af[i][2] = *(const unsigned*)&As[buf][r0][ks + 2 * c + 8];
                af[i][3] = *(const unsigned*)&As[buf][r0 + 8][ks + 2 * c + 8];
            }
            unsigned bf[NTT][2];
#pragma unroll
            for (int j = 0; j < NTT; j++) {
                int n = wn0 + j * 8 + g;
                bf[j][0] = *(const unsigned*)&Bs[buf][n][ks + 2 * c];
                bf[j][1] = *(const unsigned*)&Bs[buf][n][ks + 2 * c + 8];
            }
#pragma unroll
            for (int i = 0; i < MT; i++)
#pragma unroll
                for (int j = 0; j < NTT; j++)
                    mma_f16(acc[i][j][0], acc[i][j][1], acc[i][j][2], acc[i][j][3],
                            af[i][0], af[i][1], af[i][2], af[i][3],
                            bf[j][0], bf[j][1]);
        }
        __syncthreads();
    }

#pragma unroll
    for (int i = 0; i < MT; i++) {
#pragma unroll
        for (int j = 0; j < NTT; j++) {
            int row0 = m0 + wm0 + i * 16 + g;
            int col  = n0 + wn0 + j * 8 + 2 * c;
            float vals[4];
#pragma unroll
            for (int t = 0; t < 4; t++) {
                float vv = acc[i][j][t] * alpha;
                if (RELU) vv = fmaxf(vv, 0.f);
                vals[t] = vv;
            }
            if (OUT == 2) {
                __half* C = (__half*)Cv;
                *(__half2*)(C + (long)row0 * ldc + col) =
                    __floats2half2_rn(vals[0], vals[1]);
                *(__half2*)(C + (long)(row0 + 8) * ldc + col) =
                    __floats2half2_rn(vals[2], vals[3]);
            } else {
                float* C = (float*)Cv;
                if (OUT == 1) {
                    vals[0] = tf32f(vals[0]); vals[1] = tf32f(vals[1]);
                    vals[2] = tf32f(vals[2]); vals[3] = tf32f(vals[3]);
                }
                *(float2*)(C + (long)row0 * ldc + col)       = make_float2(vals[0], vals[1]);
                *(float2*)(C + (long)(row0 + 8) * ldc + col) = make_float2(vals[2], vals[3]);
            }
        }
    }
}

// ------------------------ fused attention kernel ---------------------------
__global__ void __launch_bounds__(128, 2)
attn_fused(const float* __restrict__ QKV, __half* __restrict__ AO,
           float* __restrict__ colpart,
           const int* __restrict__ widp, const int* __restrict__ nbp, int mode) {
    __shared__ float pool[8960];
    __shared__ float red[2][QT];
    __shared__ float sm_t[QT];
    __shared__ int   wq_s[QT], wk_s[2][KBL];
    __shared__ int   act[NBLK], actflag[NBLK], s_cnt;

    float (*B0)[68] = (float(*)[68])pool;
    float (*B1)[68] = (float(*)[68])(pool + 4352);
    float (*Vs)[72] = (float(*)[72])(pool + 4352);

    int qt = blockIdx.x, bh = blockIdx.y;
    int b = bh >> 3;
    int tid = threadIdx.x, wid = tid >> 5, lane = tid & 31;
    int g = lane >> 2, c = lane & 3;
    int wq0 = (wid & 1) * 32;
    int wk0 = (wid >> 1) * 32;
    int kgrp = wid >> 1;
    int q0 = qt * QT;
    long base = (long)b * cT * SQ + (bh & 7) * cDH;
    const float* Qp = QKV + base;
    const float* Kp = QKV + base + cF;
    const float* Vp = QKV + base + 2 * cF;
    int nbv = (mode == 1) ? __ldg(&nbp[b]) : 0;

#pragma unroll
    for (int i = 0; i < 8; i++) {
        int e = tid + i * 128;
        int r = e >> 4, cq = (e & 15) << 2;
        cpasync16(&B0[r][cq], Qp + (long)(q0 + r) * SQ + cq);
    }
    cp_commit();
    if (mode == 0 && tid < QT) wq_s[tid] = __ldg(&widp[b * cT + q0 + tid]);
    if (tid == 0) {
        int cnt = 0;
        if (mode == 0) {
            int wq_lo = __ldg(&widp[b * cT + q0]);
            int wq_hi = __ldg(&widp[b * cT + q0 + QT - 1]);
            for (int kb = 0; kb < NBLK; kb++) {
                int klo = __ldg(&widp[b * cT + kb * KBL]);
                int khi = __ldg(&widp[b * cT + kb * KBL + KBL - 1]);
                int a = (klo <= wq_hi) && (khi >= wq_lo);
                actflag[kb] = a;
                if (a) act[cnt++] = kb;
            }
        } else {
            for (int kb = 0; kb < NBLK; kb++) {
                int a = (kb * KBL < nbv);
                actflag[kb] = a;
                if (a) act[cnt++] = kb;
            }
        }
        s_cnt = cnt;
    }
    cp_wait<0>();
    __syncthreads();

    unsigned aq[2][8][4];
#pragma unroll
    for (int i = 0; i < 2; i++) {
        int r0 = wq0 + i * 16 + g;
#pragma unroll
        for (int kk = 0; kk < 8; kk++) {
            aq[i][kk][0] = __float_as_uint(B0[r0][kk * 8 + c]);
            aq[i][kk][1] = __float_as_uint(B0[r0 + 8][kk * 8 + c]);
            aq[i][kk][2] = __float_as_uint(B0[r0][kk * 8 + c + 4]);
            aq[i][kk][3] = __float_as_uint(B0[r0 + 8][kk * 8 + c + 4]);
        }
    }
    int cnt = s_cnt;
    __syncthreads();

    auto issueK = [&](int s, int kb) {
        float (*dst)[68] = s ? B1 : B0;
#pragma unroll
        for (int i = 0; i < 8; i++) {
            int e = tid + i * 128;
            int r = e >> 4, cq = (e & 15) << 2;
            cpasync16(&dst[r][cq], Kp + (long)(kb * KBL + r) * SQ + cq);
        }
        cp_commit();
        if (mode == 0 && tid < KBL)
            wk_s[s][tid] = __ldg(&widp[b * cT + kb * KBL + tid]);
    };

    float rsum[4] = {};
    if (cnt > 0) {
        issueK(0, act[0]);
        for (int ii = 0; ii < cnt; ii++) {
            if (ii + 1 < cnt) issueK((ii + 1) & 1, act[ii + 1]);
            else              cp_commit();
            cp_wait<1>();
            __syncthreads();

            int kb = act[ii];
            float (*Kb)[68] = (ii & 1) ? B1 : B0;
            const int* wk = wk_s[ii & 1];
            float sacc[2][4][4] = {};
#pragma unroll
            for (int kk = 0; kk < 8; kk++) {
                unsigned bf[4][2];
#pragma unroll
                for (int j = 0; j < 4; j++) {
                    int n = wk0 + j * 8 + g;
                    bf[j][0] = __float_as_uint(Kb[n][kk * 8 + c]);
                    bf[j][1] = __float_as_uint(Kb[n][kk * 8 + c + 4]);
                }
#pragma unroll
                for (int i = 0; i < 2; i++)
#pragma unroll
                    for (int j = 0; j < 4; j++)
                        mma_tf32(sacc[i][j][0], sacc[i][j][1], sacc[i][j][2], sacc[i][j][3],
                                 aq[i][kk][0], aq[i][kk][1], aq[i][kk][2], aq[i][kk][3],
                                 bf[j][0], bf[j][1]);
            }
#pragma unroll
            for (int i = 0; i < 2; i++)
#pragma unroll
                for (int j = 0; j < 4; j++)
#pragma unroll
                    for (int e = 0; e < 4; e++) {
                        float s = sacc[i][j][e] * 0.125f;
                        int qr = wq0 + i * 16 + g + ((e >> 1) ? 8 : 0);
                        int kc = wk0 + j * 8 + 2 * c + (e & 1);
                        bool msk = (mode == 0) ? (wk[kc] != wq_s[qr])
                                               : (kb * KBL + kc >= nbv);
                        int ri = i * 2 + (e >> 1);
                        if (!msk) rsum[ri] += __expf(s);
                    }
            __syncthreads();
        }
    }
#pragma unroll
    for (int r = 0; r < 4; r++) {
        rsum[r] += __shfl_xor_sync(0xffffffffu, rsum[r], 1);
        rsum[r] += __shfl_xor_sync(0xffffffffu, rsum[r], 2);
    }
    if (c == 0) {
#pragma unroll
        for (int r = 0; r < 4; r++)
            red[kgrp][wq0 + (r >> 1) * 16 + g + ((r & 1) ? 8 : 0)] = rsum[r];
    }
    __syncthreads();
    if (tid < QT) sm_t[tid] = 1.0f / (red[0][tid] + red[1][tid]);
    __syncthreads();

    float oacc[2][4][4] = {};
    for (int kb = 0; kb < NBLK; kb++) {
        if (!actflag[kb]) {
            if (tid < KBL)
                colpart[((long)bh * NQT + qt) * cT + kb * KBL + tid] = 0.f;
            continue;
        }
#pragma unroll
        for (int i = 0; i < 8; i++) {
            int e = tid + i * 128;
            int r = e >> 4, cq = (e & 15) << 2;
            cpasync16(&B0[r][cq], Kp + (long)(kb * KBL + r) * SQ + cq);
            cpasync16(&Vs[r][cq], Vp + (long)(kb * KBL + r) * SQ + cq);
        }
        cp_commit();
        if (mode == 0 && tid < KBL) wk_s[0][tid] = __ldg(&widp[b * cT + kb * KBL + tid]);
        cp_wait<0>();
        __syncthreads();

        float sacc[2][4][4] = {};
#pragma unroll
        for (int kk = 0; kk < 8; kk++) {
            unsigned bf[4][2];
#pragma unroll
            for (int j = 0; j < 4; j++) {
                int n = wk0 + j * 8 + g;
                bf[j][0] = __float_as_uint(B0[n][kk * 8 + c]);
                bf[j][1] = __float_as_uint(B0[n][kk * 8 + c + 4]);
            }
#pragma unroll
            for (int i = 0; i < 2; i++)
#pragma unroll
                for (int j = 0; j < 4; j++)
                    mma_tf32(sacc[i][j][0], sacc[i][j][1], sacc[i][j][2], sacc[i][j][3],
                             aq[i][kk][0], aq[i][kk][1], aq[i][kk][2], aq[i][kk][3],
                             bf[j][0], bf[j][1]);
        }
        float idr[4];
#pragma unroll
        for (int r = 0; r < 4; r++)
            idr[r] = sm_t[wq0 + (r >> 1) * 16 + g + ((r & 1) ? 8 : 0)];
#pragma unroll
        for (int i = 0; i < 2; i++)
#pragma unroll
            for (int j = 0; j < 4; j++)
#pragma unroll
                for (int e = 0; e < 4; e++) {
                    float s = sacc[i][j][e] * 0.125f;
                    int qr = wq0 + i * 16 + g + ((e >> 1) ? 8 : 0);
                    int kc = wk0 + j * 8 + 2 * c + (e & 1);
                    bool msk = (mode == 0) ? (wk_s[0][kc] != wq_s[qr])
                                           : (kb * KBL + kc >= nbv);
                    int ri = i * 2 + (e >> 1);
                    float ev = msk ? 0.f : __expf(s);
                    sacc[i][j][e] = tf32f(ev * idr[ri]);
                }
        __syncthreads();
#pragma unroll
        for (int i = 0; i < 2; i++)
#pragma unroll
            for (int j = 0; j < 4; j++) {
                int qr = wq0 + i * 16 + g;
                int kc = wk0 + j * 8 + 2 * c;
                *(float2*)&B0[qr][kc]     = make_float2(sacc[i][j][0], sacc[i][j][1]);
                *(float2*)&B0[qr + 8][kc] = make_float2(sacc[i][j][2], sacc[i][j][3]);
            }
        __syncthreads();
        if (tid < KBL) {
            float cs = 0.f;
#pragma unroll 8
            for (int qq = 0; qq < QT; qq++) cs += B0[qq][tid];
            colpart[((long)bh * NQT + qt) * cT + kb * KBL + tid] = cs;
        }
#pragma unroll
        for (int kk = 0; kk < 8; kk++) {
            unsigned af[2][4], bf[4][2];
#pragma unroll
            for (int i = 0; i < 2; i++) {
                int r0 = wq0 + i * 16 + g;
                af[i][0] = __float_as_uint(B0[r0][kk * 8 + c]);
                af[i][1] = __float_as_uint(B0[r0 + 8][kk * 8 + c]);
                af[i][2] = __float_as_uint(B0[r0][kk * 8 + c + 4]);
                af[i][3] = __float_as_uint(B0[r0 + 8][kk * 8 + c + 4]);
            }
#pragma unroll
            for (int j = 0; j < 4; j++) {
                int n = wk0 + j * 8 + g;
                bf[j][0] = __float_as_uint(Vs[kk * 8 + c][n]);
                bf[j][1] = __float_as_uint(Vs[kk * 8 + c + 4][n]);
            }
#pragma unroll
            for (int i = 0; i < 2; i++)
#pragma unroll
                for (int j = 0; j < 4; j++)
                    mma_tf32(oacc[i][j][0], oacc[i][j][1], oacc[i][j][2], oacc[i][j][3],
                             af[i][0], af[i][1], af[i][2], af[i][3],
                             bf[j][0], bf[j][1]);
        }
        __syncthreads();
    }

#pragma unroll
    for (int i = 0; i < 2; i++)
#pragma unroll
        for (int j = 0; j < 4; j++) {
            int qg = q0 + wq0 + i * 16 + g;
            int dh = wk0 + j * 8 + 2 * c;
            long o0 = ((long)b * cT + qg) * cF + (bh & 7) * cDH + dh;
            *(__half2*)&AO[o0] = __floats2half2_rn(oacc[i][j][0], oacc[i][j][1]);
            *(__half2*)&AO[o0 + 8L * cF] = __floats2half2_rn(oacc[i][j][2], oacc[i][j][3]);
        }
}

// -------------------- colsum partial reduction -> score --------------------
__global__ void colreduce(const float* __restrict__ cp, float* __restrict__ outv,
                          float scale) {
    int t = blockIdx.x * 256 + threadIdx.x;
    if (t >= BT) return;
    int b = t / cT, k = t - b * cT;
    float s = 0.f;
    for (int h = 0; h < cH; h++)
#pragma unroll
        for (int q = 0; q < NQT; q++)
            s += cp[(((long)(b * cH + h)) * NQT + q) * cT + k];
    outv[t] = s * scale;
}

// ------------------- window aggregation: pre[b,w,:] ------------------------
__global__ void pre_kernel(const float* __restrict__ lx, const float* __restrict__ ls,
                           const int* __restrict__ nbarr, const int* __restrict__ ws,
                           float* __restrict__ pre) {
    int b = blockIdx.y, w = blockIdx.x, tid = threadIdx.x;
    float4 acc = make_float4(0.f, 0.f, 0.f, 0.f);
    if (w < nbarr[b]) {
        int s = ws[b * (cT + 1) + w];
        int e = ws[b * (cT + 1) + w + 1];
        for (int t = s; t < e; t++) {
            float sc = __ldg(&ls[b * cT + t]);
            float4 v = ((const float4*)(lx + ((long)b * cT + t) * cF))[tid];
            acc.x = fmaf(v.x, sc, acc.x); acc.y = fmaf(v.y, sc, acc.y);
            acc.z = fmaf(v.z, sc, acc.z); acc.w = fmaf(v.w, sc, acc.w);
        }
    }
    ((float4*)(pre + ((long)b * cT + w) * cF))[tid] = acc;
}

// --------------------------- misc elementwise ------------------------------
__global__ void scale_kernel(float* __restrict__ yx, const float* __restrict__ wise) {
    long row = blockIdx.x;
    float sc = wise[row];
    float4 v = ((const float4*)(yx + row * cF))[threadIdx.x];
    v.x *= sc; v.y *= sc; v.z *= sc; v.w *= sc;
    ((float4*)(yx + row * cF))[threadIdx.x] = v;
}

__global__ void final_data(const float* __restrict__ lx, const float* __restrict__ gy,
                           const int* __restrict__ wid, float* __restrict__ outd) {
    long i = blockIdx.x;
    int b = (int)(i / cT);
    int w = wid[i];
    float4 a = ((const float4*)(lx + i * cF))[threadIdx.x];
    float4 g = ((const float4*)(gy + ((long)b * cT + w) * cF))[threadIdx.x];
    a.x += g.x; a.y += g.y; a.z += g.z; a.w += g.w;
    ((float4*)(outd + i * cF))[threadIdx.x] = a;
}

__global__ void final_attn(const float* __restrict__ ls, const float* __restrict__ h2,
                           const int* __restrict__ wid, float* __restrict__ outa) {
    int b = blockIdx.x, tid = threadIdx.x;
    float xv[3];
#pragma unroll
    for (int i = 0; i < 3; i++) {
        int t = tid + i * 256;
        xv[i] = ls[b * cT + t] * h2[b * cT + wid[b * cT + t]];
    }
    float mx = redMax256(fmaxf(fmaxf(xv[0], xv[1]), xv[2]));
    float e[3];
    float s = 0.f;
#pragma unroll
    for (int i = 0; i < 3; i++) { e[i] = expf(xv[i] - mx); s += e[i]; }
    s = redSum256(s);
    float inv = 1.0f / s;
#pragma unroll
    for (int i = 0; i < 3; i++) outa[b * cT + tid + i * 256] = e[i] * inv;
}

// ------------------------------ host side ----------------------------------
static void run_transformer(const __half* xin_h, const float* xin_f,
                            const __half* W,
                            float* yout, float* score, int mode,
                            float* qkv, __half* ao, float* pj, __half* y, __half* h,
                            float* colpart, const int* wid, const int* nb) {
    gemm_h<128, 128, 128, 2, 2, false, 1><<<dim3(SQ / 128, BT / 128, 1), 128>>>(
        xin_h, W + OFF_QKV, qkv, cF, cF, cF, SQ, 1.f);
    attn_fused<<<dim3(NQT, cB * cH), 128>>>(qkv, ao, colpart, wid, nb, mode);
    gemm_h<128, 128, 128, 2, 2, false, 0><<<dim3(cF / 128, BT / 128, 1), 128>>>(
        ao, W + OFF_WO, pj, cF, cF, cF, cF, 1.f);
    colreduce<<<(BT + 255) / 256, 256>>>(colpart, score, 1.0f / (cH * cT));
    // y = LN(xin_f + pj): float copy in yout (residual), half twin for FFN
    ln_ff<<<BT, 128>>>(xin_f, pj, yout, y);
    gemm_h<128, 128, 128, 2, 2, true, 2><<<dim3(cFF / 128, BT / 128, 1), 128>>>(
        y, W + OFF_W1, h, cF, cF, cF, cFF, 1.f);
    gemm_h<128, 128, 128, 2, 2, false, 0><<<dim3(cF / 128, BT / 128, 1), 128>>>(
        h, W + OFF_W2, pj, cFF, cFF, cFF, cF, 1.f);
    ln_ff<<<BT, 128>>>(yout, pj, yout, nullptr);
}

extern "C" void kernel_launch(void* const* d_in, const int* in_sizes, int n_in,
                              void* d_out, int out_size) {
    (void)in_sizes; (void)n_in; (void)out_size;
    const float* x   = (const float*)d_in[0];
    const float* hs  = (const float*)d_in[1];
    const float* msk = (const float*)d_in[2];

    float* out      = (float*)d_out;
    float* out_thr  = out + (long)BT * cF;
    float* out_attn = out_thr + cB;

    __half *xl, *ao, *y, *h, *wt;
    float *qkv, *pj, *lx, *gy, *pre, *xf, *ls, *h2, *wise, *cp;
    int *wid, *nb, *ws;
    cudaGetSymbolAddress((void**)&xl,   g_xl);
    cudaGetSymbolAddress((void**)&qkv,  g_qkv);
    cudaGetSymbolAddress((void**)&ao,   g_ao);
    cudaGetSymbolAddress((void**)&pj,   g_pj);
    cudaGetSymbolAddress((void**)&y,    g_y);
    cudaGetSymbolAddress((void**)&h,    g_h);
    cudaGetSymbolAddress((void**)&lx,   g_lx);
    cudaGetSymbolAddress((void**)&gy,   g_gy);
    cudaGetSymbolAddress((void**)&pre,  g_pre);
    cudaGetSymbolAddress((void**)&xf,   g_xf);
    cudaGetSymbolAddress((void**)&ls,   g_ls);
    cudaGetSymbolAddress((void**)&h2,   g_h2);
    cudaGetSymbolAddress((void**)&wise, g_wise);
    cudaGetSymbolAddress((void**)&cp,   g_cp);
    cudaGetSymbolAddress((void**)&wt,   g_wt);
    cudaGetSymbolAddress((void**)&wid,  g_wid);
    cudaGetSymbolAddress((void**)&nb,   g_nb);
    cudaGetSymbolAddress((void**)&ws,   g_ws);

    // 0. transpose + fp16-convert all 12 weights
    for (int t = 0; t < 2; t++) {
        __half* tb = wt + (long)t * WSET;
        for (int jj = 0; jj < 3; jj++)
            cvtT<<<dim3(cF / 32, cF / 32), dim3(32, 8)>>>(
                (const float*)d_in[3 + t * 6 + jj],
                tb + OFF_QKV + (long)jj * cF * cF, cF, cF);
        cvtT<<<dim3(cF / 32, cF / 32), dim3(32, 8)>>>(
            (const float*)d_in[3 + t * 6 + 3], tb + OFF_WO, cF, cF);
        cvtT<<<dim3(cF / 32, cFF / 32), dim3(32, 8)>>>(
            (const float*)d_in[3 + t * 6 + 4], tb + OFF_W1, cF, cFF);
        cvtT<<<dim3(cFF / 32, cF / 32), dim3(32, 8)>>>(
            (const float*)d_in[3 + t * 6 + 5], tb + OFF_W2, cFF, cF);
    }

    // 1. masks
    masks_kernel<<<cB, 256>>>(hs, msk, out_thr, wid, nb, ws, wise);
    // 2. xf = LN(x) float, xl = half twin
    ln_ff<<<BT, 128>>>(x, nullptr, xf, xl);
    // 3. local transformer
    run_transformer(xl, xf, wt, lx, ls, /*mode=*/0,
                    qkv, ao, pj, y, h, cp, wid, nb);
    // 4. local_x *= wise
    scale_kernel<<<BT, 128>>>(lx, wise);
    // 5. pre aggregation
    pre_kernel<<<dim3(cT, cB), 128>>>(lx, ls, nb, ws, pre);
    // 6. xf = LN(pre) float, xl = half twin
    ln_ff<<<BT, 128>>>(pre, nullptr, xf, xl);
    // 7. global transformer
    run_transformer(xl, xf, wt + WSET, gy, h2, /*mode=*/1,
                    qkv, ao, pj, y, h, cp, wid, nb);
    // 8/9. outputs
    final_data<<<BT, 128>>>(lx, gy, wid, out);
    final_attn<<<cB, 256>>>(ls, h2, wid, out_attn);
}

// round 17
// speedup vs baseline: 1.7680x; 1.0478x over previous
#include <cuda_runtime.h>
#include <cuda_fp16.h>
#include <math.h>

// ---------------------------------------------------------------------------
// DWFormerBlock round 17: attention scores move to FP16 m16n8k16 (Q,K stored
// half from the QKV GEMM; V stays float for the proven tf32 A*V path; P is
// stored half, exactly representable in tf32). wise-scaling fused into the
// local transformer's final LN. Dense GEMMs unchanged from R16 (fp16).
// ---------------------------------------------------------------------------

constexpr int cB  = 16;
constexpr int cT  = 768;
constexpr int cF  = 512;
constexpr int cFF = 2048;
constexpr int cH  = 8;
constexpr int cDH = 64;
constexpr int BT  = cB * cT;       // 12288
constexpr float NEGVAL = -1e30f;

constexpr int QT   = 64;
constexpr int KBL  = 64;
constexpr int NQT  = cT / QT;      // 12
constexpr int NBLK = cT / KBL;     // 12
constexpr int SQK  = 2 * cF;       // qk row stride (1024 halves)

constexpr long OFF_QKV = 0;                        // [1536][512] half (Wq|Wk|Wv rows)
constexpr long OFF_WO  = (long)(3 * cF) * cF;
constexpr long OFF_W1  = OFF_WO + (long)cF * cF;
constexpr long OFF_W2  = OFF_W1 + (long)cFF * cF;
constexpr long WSET    = OFF_W2 + (long)cF * cFF;

// ------------------------------- scratch -----------------------------------
__device__ __half g_xl [BT * cF];
__device__ __half g_qk [(long)BT * SQK];
__device__ float  g_v  [BT * cF];
__device__ __half g_ao [BT * cF];
__device__ float  g_pj [BT * cF];
__device__ __half g_y  [BT * cF];
__device__ __half g_h  [BT * cFF];
__device__ float  g_lx [BT * cF];
__device__ float  g_gy [BT * cF];
__device__ float  g_pre[BT * cF];
__device__ float  g_xf [BT * cF];
__device__ float  g_ls [BT];
__device__ float  g_h2 [BT];
__device__ float  g_wise[BT];
__device__ float  g_cp [(long)cB * cH * NQT * cT];
__device__ __half g_wt [2 * WSET];
__device__ int    g_wid[BT];
__device__ int    g_nb [cB];
__device__ int    g_ws [cB * (cT + 1)];

// --------------------------- small helpers ---------------------------------
__device__ __forceinline__ unsigned tf32r(float f) {
    unsigned u;
    asm("cvt.rna.tf32.f32 %0, %1;" : "=r"(u) : "f"(f));
    return u;
}
__device__ __forceinline__ float tf32f(float f) {
    return __uint_as_float(tf32r(f));
}

__device__ __forceinline__ void mma_tf32(float& d0, float& d1, float& d2, float& d3,
                                         unsigned a0, unsigned a1, unsigned a2, unsigned a3,
                                         unsigned b0, unsigned b1) {
    asm volatile(
        "mma.sync.aligned.m16n8k8.row.col.f32.tf32.tf32.f32 "
        "{%0,%1,%2,%3}, {%4,%5,%6,%7}, {%8,%9}, {%0,%1,%2,%3};"
        : "+f"(d0), "+f"(d1), "+f"(d2), "+f"(d3)
        : "r"(a0), "r"(a1), "r"(a2), "r"(a3), "r"(b0), "r"(b1));
}

__device__ __forceinline__ void mma_f16(float& d0, float& d1, float& d2, float& d3,
                                        unsigned a0, unsigned a1, unsigned a2, unsigned a3,
                                        unsigned b0, unsigned b1) {
    asm volatile(
        "mma.sync.aligned.m16n8k16.row.col.f32.f16.f16.f32 "
        "{%0,%1,%2,%3}, {%4,%5,%6,%7}, {%8,%9}, {%0,%1,%2,%3};"
        : "+f"(d0), "+f"(d1), "+f"(d2), "+f"(d3)
        : "r"(a0), "r"(a1), "r"(a2), "r"(a3), "r"(b0), "r"(b1));
}

__device__ __forceinline__ void cpasync16(void* sdst, const void* gsrc) {
    unsigned s = (unsigned)__cvta_generic_to_shared(sdst);
    asm volatile("cp.async.cg.shared.global [%0], [%1], 16;" :: "r"(s), "l"(gsrc));
}
__device__ __forceinline__ void cp_commit() {
    asm volatile("cp.async.commit_group;");
}
template <int N>
__device__ __forceinline__ void cp_wait() {
    asm volatile("cp.async.wait_group %0;" :: "n"(N));
}

__device__ __forceinline__ float redMax256(float v) {
    __shared__ float sm[8];
#pragma unroll
    for (int o = 16; o > 0; o >>= 1) v = fmaxf(v, __shfl_xor_sync(0xffffffffu, v, o));
    if ((threadIdx.x & 31) == 0) sm[threadIdx.x >> 5] = v;
    __syncthreads();
    if (threadIdx.x == 0) {
        float m = sm[0];
#pragma unroll
        for (int i = 1; i < 8; i++) m = fmaxf(m, sm[i]);
        sm[0] = m;
    }
    __syncthreads();
    float r = sm[0];
    __syncthreads();
    return r;
}

__device__ __forceinline__ float redSum256(float v) {
    __shared__ float sm[8];
#pragma unroll
    for (int o = 16; o > 0; o >>= 1) v += __shfl_xor_sync(0xffffffffu, v, o);
    if ((threadIdx.x & 31) == 0) sm[threadIdx.x >> 5] = v;
    __syncthreads();
    if (threadIdx.x == 0) {
        float s = 0.f;
#pragma unroll
        for (int i = 0; i < 8; i++) s += sm[i];
        sm[0] = s;
    }
    __syncthreads();
    float r = sm[0];
    __syncthreads();
    return r;
}

// ---------------- weight transpose + fp16 convert (tiled) ------------------
__global__ void cvtT(const float* __restrict__ src, __half* __restrict__ dst,
                     int K, int N) {
    __shared__ float t[32][33];
    int k0 = blockIdx.x * 32, n0 = blockIdx.y * 32;
    int tx = threadIdx.x, ty = threadIdx.y;
#pragma unroll
    for (int i = 0; i < 4; i++)
        t[ty + 8 * i][tx] = src[(long)(k0 + ty + 8 * i) * N + n0 + tx];
    __syncthreads();
#pragma unroll
    for (int i = 0; i < 4; i++)
        dst[(long)(n0 + ty + 8 * i) * K + k0 + tx] =
            __float2half_rn(t[tx][ty + 8 * i]);
}

// ------------------------------- masks kernel ------------------------------
__global__ void masks_kernel(const float* __restrict__ hs, const float* __restrict__ msk,
                             float* __restrict__ thr_out, int* __restrict__ wid,
                             int* __restrict__ nbarr, int* __restrict__ ws,
                             float* __restrict__ wise) {
    int b = blockIdx.x, tid = threadIdx.x;
    __shared__ float ss[1024];
    __shared__ int a1[cT];
    __shared__ int x3[cT];
    __shared__ float red[256];
    __shared__ float sthr;

    for (int i = tid; i < 1024; i += 256)
        ss[i] = (i < cT) ? hs[b * cT + i] : 3.402823466e38f;
    __syncthreads();

    for (int k2 = 2; k2 <= 1024; k2 <<= 1) {
        for (int j = k2 >> 1; j > 0; j >>= 1) {
            for (int i = tid; i < 1024; i += 256) {
                int l = i ^ j;
                if (l > i) {
                    float a = ss[i], c = ss[l];
                    bool up = ((i & k2) == 0);
                    if ((a > c) == up) { ss[i] = c; ss[l] = a; }
                }
            }
            __syncthreads();
        }
    }

    float m1 = 0.f;
    for (int i = tid; i < cT; i += 256) m1 += 1.0f - msk[b * cT + i];
    red[tid] = m1; __syncthreads();
    for (int s = 128; s > 0; s >>= 1) {
        if (tid < s) red[tid] += red[tid + s];
        __syncthreads();
    }
    if (tid == 0) {
        float mm = red[0];
        int med = (int)(mm * 0.5f + (float)cT - mm);
        if (med > cT - 1) med = cT - 1;
        if (med < 0) med = 0;
        sthr = ss[med];
        thr_out[b] = sthr;
    }
    __syncthreads();
    float thr = sthr;

    for (int i = tid; i < cT; i += 256) {
        int keep = (hs[b * cT + i] >= thr) ? 1 : 0;
        a1[i] = keep;
        wise[b * cT + i] = keep ? 1.0f : 0.85f;
    }
    __syncthreads();
    for (int i = tid; i < cT; i += 256) {
        int x2 = (i < cT - 1) ? a1[i + 1] : (1 - a1[cT - 1]);
        x3[i] = (x2 != a1[i]) ? 1 : 0;
    }
    __syncthreads();
    if (tid == 0) {
        int c = 0;
        ws[b * (cT + 1)] = 0;
        int prev = 0;
        for (int t = 0; t < cT; t++) {
            int xt = x3[t];
            int xm = (xt == 1 && prev == 1) ? 0 : xt;
            if (t == cT - 1) xm = 1;
            prev = xt;
            wid[b * cT + t] = c;
            if (xm) { c++; ws[b * (cT + 1) + c] = t + 1; }
        }
        nbarr[b] = c;
    }
}

// ------------------------------ layernorm ----------------------------------
__device__ __forceinline__ float4 ln_core(float4 v) {
    float s = v.x + v.y + v.z + v.w;
    float q = v.x * v.x + v.y * v.y + v.z * v.z + v.w * v.w;
    __shared__ float rs[4], rq[4];
#pragma unroll
    for (int o = 16; o > 0; o >>= 1) {
        s += __shfl_down_sync(0xffffffffu, s, o);
        q += __shfl_down_sync(0xffffffffu, q, o);
    }
    int w = threadIdx.x >> 5;
    if ((threadIdx.x & 31) == 0) { rs[w] = s; rq[w] = q; }
    __syncthreads();
    s = rs[0] + rs[1] + rs[2] + rs[3];
    q = rq[0] + rq[1] + rq[2] + rq[3];
    float mean = s * (1.0f / cF);
    float var  = q * (1.0f / cF) - mean * mean;
    float inv  = rsqrtf(var + 1e-5f);
    return make_float4((v.x - mean) * inv, (v.y - mean) * inv,
                       (v.z - mean) * inv, (v.w - mean) * inv);
}

// Y(float, optional) and Yh(half twin, optional) = LN(X + R) [* wise[row]]
__global__ void ln_ff(const float* __restrict__ X, const float* __restrict__ R,
                      float* __restrict__ Y, __half* __restrict__ Yh,
                      const float* __restrict__ wisep) {
    long row = blockIdx.x;
    float4 v = ((const float4*)(X + row * cF))[threadIdx.x];
    if (R) {
        float4 r = ((const float4*)(R + row * cF))[threadIdx.x];
        v.x += r.x; v.y += r.y; v.z += r.z; v.w += r.w;
    }
    float4 o = ln_core(v);
    if (wisep) {
        float sc = wisep[row];
        o.x *= sc; o.y *= sc; o.z *= sc; o.w *= sc;
    }
    if (Y) ((float4*)(Y + row * cF))[threadIdx.x] = o;
    if (Yh) {
        __half2* oh = (__half2*)(Yh + row * cF);
        oh[2 * threadIdx.x]     = __floats2half2_rn(o.x, o.y);
        oh[2 * threadIdx.x + 1] = __floats2half2_rn(o.z, o.w);
    }
}

// --------------------------- FP16 tensor GEMM ------------------------------
// A [M][K] half row-major, Bt [N][K] half row-major. BK=32 halves,
// 2-stage cp.async (issue-before-wait), warp-parity k16 stagger.
// OUT: 0 = float, 1 = float tf32-rounded, 2 = half.
template <int BM, int BN, int NT, int WM, int WN, bool RELU, int OUT>
__global__ void __launch_bounds__(NT, 2)
gemm_h(const __half* __restrict__ A, const __half* __restrict__ Bt, void* Cv,
       int K, int lda, int ldb, int ldc, float alpha) {
    constexpr int BK   = 32;
    constexpr int BKPh = BK + 8;
    constexpr int MT   = BM / WM / 16;
    constexpr int NTT  = BN / WN / 8;
    constexpr int AI   = BM * BK / 8 / NT;
    constexpr int BI   = BN * BK / 8 / NT;
    static_assert(AI * NT * 8 == BM * BK, "A tile");
    static_assert(BI * NT * 8 == BN * BK, "B tile");

    __shared__ __half As[2][BM][BKPh];
    __shared__ __half Bs[2][BN][BKPh];

    int tid  = threadIdx.x;
    int wid  = tid >> 5, lane = tid & 31;
    int g    = lane >> 2, c = lane & 3;
    int wm0  = (wid % WM) * (BM / WM);
    int wn0  = (wid / WM) * (BN / WN);
    int m0   = blockIdx.y * BM, n0 = blockIdx.x * BN;
    int kflip = (wid & 1) ? 16 : 0;

    float acc[MT][NTT][4] = {};

    auto issue = [&](int s, int k0) {
#pragma unroll
        for (int i = 0; i < AI; i++) {
            int e = tid + i * NT;
            int m = e >> 2, kq = (e & 3) << 3;
            cpasync16(&As[s][m][kq], A + (long)(m0 + m) * lda + k0 + kq);
        }
#pragma unroll
        for (int i = 0; i < BI; i++) {
            int e = tid + i * NT;
            int n = e >> 2, kq = (e & 3) << 3;
            cpasync16(&Bs[s][n][kq], Bt + (long)(n0 + n) * ldb + k0 + kq);
        }
        cp_commit();
    };

    int KT = K / BK;
    issue(0, 0);

    for (int it = 0; it < KT; it++) {
        if (it + 1 < KT) issue((it + 1) & 1, (it + 1) * BK);
        else             cp_commit();
        cp_wait<1>();
        __syncthreads();

        int buf = it & 1;
#pragma unroll
        for (int kx = 0; kx < BK; kx += 16) {
            int ks = kx ^ kflip;
            unsigned af[MT][4];
#pragma unroll
            for (int i = 0; i < MT; i++) {
                int r0 = wm0 + i * 16 + g;
                af[i][0] = *(const unsigned*)&As[buf][r0][ks + 2 * c];
                af[i][1] = *(const unsigned*)&As[buf][r0 + 8][ks + 2 * c];
                af[i][2] = *(const unsigned*)&As[buf][r0][ks + 2 * c + 8];
                af[i][3] = *(const unsigned*)&As[buf][r0 + 8][ks + 2 * c + 8];
            }
            unsigned bf[NTT][2];
#pragma unroll
            for (int j = 0; j < NTT; j++) {
                int n = wn0 + j * 8 + g;
                bf[j][0] = *(const unsigned*)&Bs[buf][n][ks + 2 * c];
                bf[j][1] = *(const unsigned*)&Bs[buf][n][ks + 2 * c + 8];
            }
#pragma unroll
            for (int i = 0; i < MT; i++)
#pragma unroll
                for (int j = 0; j < NTT; j++)
                    mma_f16(acc[i][j][0], acc[i][j][1], acc[i][j][2], acc[i][j][3],
                            af[i][0], af[i][1], af[i][2], af[i][3],
                            bf[j][0], bf[j][1]);
        }
        __syncthreads();
    }

#pragma unroll
    for (int i = 0; i < MT; i++) {
#pragma unroll
        for (int j = 0; j < NTT; j++) {
            int row0 = m0 + wm0 + i * 16 + g;
            int col  = n0 + wn0 + j * 8 + 2 * c;
            float vals[4];
#pragma unroll
            for (int t = 0; t < 4; t++) {
                float vv = acc[i][j][t] * alpha;
                if (RELU) vv = fmaxf(vv, 0.f);
                vals[t] = vv;
            }
            if (OUT == 2) {
                __half* C = (__half*)Cv;
                *(__half2*)(C + (long)row0 * ldc + col) =
                    __floats2half2_rn(vals[0], vals[1]);
                *(__half2*)(C + (long)(row0 + 8) * ldc + col) =
                    __floats2half2_rn(vals[2], vals[3]);
            } else {
                float* C = (float*)Cv;
                if (OUT == 1) {
                    vals[0] = tf32f(vals[0]); vals[1] = tf32f(vals[1]);
                    vals[2] = tf32f(vals[2]); vals[3] = tf32f(vals[3]);
                }
                *(float2*)(C + (long)row0 * ldc + col)       = make_float2(vals[0], vals[1]);
                *(float2*)(C + (long)(row0 + 8) * ldc + col) = make_float2(vals[2], vals[3]);
            }
        }
    }
}

// ------------------------ fused attention kernel ---------------------------
// Q,K half (stride SQK); V float (stride cF). S via f16 m16n8k16 (4 k-steps),
// P stored half (exact in tf32), A*V via tf32 m16n8k8 with cvt-on-load.
// Block skipping + ping-pong phase 1 as before.
__global__ void __launch_bounds__(128, 2)
attn_fused(const __half* __restrict__ QK, const float* __restrict__ Vf,
           __half* __restrict__ AO, float* __restrict__ colpart,
           const int* __restrict__ widp, const int* __restrict__ nbp, int mode) {
    // pool layout (bytes):
    //   [0,9216)        Qs   half [64][72]
    //   [9216,18432)    Kh0  half [64][72]   (phase2: reused as P half)
    //   [18432,36864)   phase1: Kh1 half [64][72] (first 9216)
    //                   phase2: Vs float [64][72]
    __shared__ __align__(16) unsigned char pool[36864];
    __shared__ float red[2][QT];
    __shared__ float sm_t[QT];
    __shared__ int   wq_s[QT], wk_s[2][KBL];
    __shared__ int   act[NBLK], actflag[NBLK], s_cnt;

    __half (*Qs)[72]  = (__half(*)[72])pool;
    __half (*Kh0)[72] = (__half(*)[72])(pool + 9216);
    __half (*Kh1)[72] = (__half(*)[72])(pool + 18432);
    __half (*Ph)[72]  = Kh0;
    float  (*Vs)[72]  = (float(*)[72])(pool + 18432);

    int qt = blockIdx.x, bh = blockIdx.y;
    int b = bh >> 3;
    int tid = threadIdx.x, wid = tid >> 5, lane = tid & 31;
    int g = lane >> 2, c = lane & 3;
    int wq0 = (wid & 1) * 32;
    int wk0 = (wid >> 1) * 32;
    int kgrp = wid >> 1;
    int q0 = qt * QT;
    const __half* Qp = QK + (long)b * cT * SQK + (bh & 7) * cDH;
    const __half* Kp = Qp + cF;
    const float*  Vp = Vf + (long)b * cT * cF + (bh & 7) * cDH;
    int nbv = (mode == 1) ? __ldg(&nbp[b]) : 0;
    int kflip = (wid & 1) ? 16 : 0;

    // ---- stage Q tile (64 rows x 64 halves = 8 chunks/row) ----
#pragma unroll
    for (int i = 0; i < 4; i++) {
        int e = tid + i * 128;
        int r = e >> 3, ch = (e & 7) << 3;
        cpasync16(&Qs[r][ch], Qp + (long)(q0 + r) * SQK + ch);
    }
    cp_commit();
    if (mode == 0 && tid < QT) wq_s[tid] = __ldg(&widp[b * cT + q0 + tid]);
    if (tid == 0) {
        int cnt = 0;
        if (mode == 0) {
            int wq_lo = __ldg(&widp[b * cT + q0]);
            int wq_hi = __ldg(&widp[b * cT + q0 + QT - 1]);
            for (int kb = 0; kb < NBLK; kb++) {
                int klo = __ldg(&widp[b * cT + kb * KBL]);
                int khi = __ldg(&widp[b * cT + kb * KBL + KBL - 1]);
                int a = (klo <= wq_hi) && (khi >= wq_lo);
                actflag[kb] = a;
                if (a) act[cnt++] = kb;
            }
        } else {
            for (int kb = 0; kb < NBLK; kb++) {
                int a = (kb * KBL < nbv);
                actflag[kb] = a;
                if (a) act[cnt++] = kb;
            }
        }
        s_cnt = cnt;
    }
    cp_wait<0>();
    __syncthreads();

    // A fragments (f16): 4 k16 steps over dh=64
    unsigned aq[2][4][4];
#pragma unroll
    for (int i = 0; i < 2; i++) {
        int r0 = wq0 + i * 16 + g;
#pragma unroll
        for (int kk = 0; kk < 4; kk++) {
            aq[i][kk][0] = *(const unsigned*)&Qs[r0][kk * 16 + 2 * c];
            aq[i][kk][1] = *(const unsigned*)&Qs[r0 + 8][kk * 16 + 2 * c];
            aq[i][kk][2] = *(const unsigned*)&Qs[r0][kk * 16 + 2 * c + 8];
            aq[i][kk][3] = *(const unsigned*)&Qs[r0 + 8][kk * 16 + 2 * c + 8];
        }
    }
    int cnt = s_cnt;
    __syncthreads();

    auto issueK = [&](int s, int kb) {
        __half (*dst)[72] = s ? Kh1 : Kh0;
#pragma unroll
        for (int i = 0; i < 4; i++) {
            int e = tid + i * 128;
            int r = e >> 3, ch = (e & 7) << 3;
            cpasync16(&dst[r][ch], Kp + (long)(kb * KBL + r) * SQK + ch);
        }
        cp_commit();
        if (mode == 0 && tid < KBL)
            wk_s[s][tid] = __ldg(&widp[b * cT + kb * KBL + tid]);
    };

    // S computation helper (fp16): sacc += Q . K^T
    auto computeS = [&](__half (*Kb)[72], float sacc[2][4][4]) {
#pragma unroll
        for (int kx = 0; kx < 4; kx++) {
            int kk = (kx * 16) ^ kflip;      // column offset with warp stagger
            unsigned bf[4][2];
#pragma unroll
            for (int j = 0; j < 4; j++) {
                int n = wk0 + j * 8 + g;
                bf[j][0] = *(const unsigned*)&Kb[n][kk + 2 * c];
                bf[j][1] = *(const unsigned*)&Kb[n][kk + 2 * c + 8];
            }
#pragma unroll
            for (int i = 0; i < 2; i++)
#pragma unroll
                for (int j = 0; j < 4; j++)
                    mma_f16(sacc[i][j][0], sacc[i][j][1], sacc[i][j][2], sacc[i][j][3],
                            aq[i][(kk >> 4)][0], aq[i][(kk >> 4)][1],
                            aq[i][(kk >> 4)][2], aq[i][(kk >> 4)][3],
                            bf[j][0], bf[j][1]);
        }
    };

    // ---- phase 1: row denominators over active blocks ----
    float rsum[4] = {};
    if (cnt > 0) {
        issueK(0, act[0]);
        for (int ii = 0; ii < cnt; ii++) {
            if (ii + 1 < cnt) issueK((ii + 1) & 1, act[ii + 1]);
            else              cp_commit();
            cp_wait<1>();
            __syncthreads();

            int kb = act[ii];
            __half (*Kb)[72] = (ii & 1) ? Kh1 : Kh0;
            const int* wk = wk_s[ii & 1];
            float sacc[2][4][4] = {};
            computeS(Kb, sacc);
#pragma unroll
            for (int i = 0; i < 2; i++)
#pragma unroll
                for (int j = 0; j < 4; j++)
#pragma unroll
                    for (int e = 0; e < 4; e++) {
                        float s = sacc[i][j][e] * 0.125f;
                        int qr = wq0 + i * 16 + g + ((e >> 1) ? 8 : 0);
                        int kc = wk0 + j * 8 + 2 * c + (e & 1);
                        bool msk = (mode == 0) ? (wk[kc] != wq_s[qr])
                                               : (kb * KBL + kc >= nbv);
                        int ri = i * 2 + (e >> 1);
                        if (!msk) rsum[ri] += __expf(s);
                    }
            __syncthreads();
        }
    }
#pragma unroll
    for (int r = 0; r < 4; r++) {
        rsum[r] += __shfl_xor_sync(0xffffffffu, rsum[r], 1);
        rsum[r] += __shfl_xor_sync(0xffffffffu, rsum[r], 2);
    }
    if (c == 0) {
#pragma unroll
        for (int r = 0; r < 4; r++)
            red[kgrp][wq0 + (r >> 1) * 16 + g + ((r & 1) ? 8 : 0)] = rsum[r];
    }
    __syncthreads();
    if (tid < QT) sm_t[tid] = 1.0f / (red[0][tid] + red[1][tid]);
    __syncthreads();

    // ---- phase 2: P, colsums, out (active blocks only) ----
    float oacc[2][4][4] = {};
    for (int kb = 0; kb < NBLK; kb++) {
        if (!actflag[kb]) {
            if (tid < KBL)
                colpart[((long)bh * NQT + qt) * cT + kb * KBL + tid] = 0.f;
            continue;
        }
        // load K (half) and V (float) concurrently
#pragma unroll
        for (int i = 0; i < 4; i++) {
            int e = tid + i * 128;
            int r = e >> 3, ch = (e & 7) << 3;
            cpasync16(&Kh0[r][ch], Kp + (long)(kb * KBL + r) * SQK + ch);
        }
#pragma unroll
        for (int i = 0; i < 8; i++) {
            int e = tid + i * 128;
            int r = e >> 4, ch = (e & 15) << 2;
            cpasync16(&Vs[r][ch], Vp + (long)(kb * KBL + r) * cF + ch);
        }
        cp_commit();
        if (mode == 0 && tid < KBL) wk_s[0][tid] = __ldg(&widp[b * cT + kb * KBL + tid]);
        cp_wait<0>();
        __syncthreads();

        float sacc[2][4][4] = {};
        computeS(Kh0, sacc);
        float idr[4];
#pragma unroll
        for (int r = 0; r < 4; r++)
            idr[r] = sm_t[wq0 + (r >> 1) * 16 + g + ((r & 1) ? 8 : 0)];
#pragma unroll
        for (int i = 0; i < 2; i++)
#pragma unroll
            for (int j = 0; j < 4; j++)
#pragma unroll
                for (int e = 0; e < 4; e++) {
                    float s = sacc[i][j][e] * 0.125f;
                    int qr = wq0 + i * 16 + g + ((e >> 1) ? 8 : 0);
                    int kc = wk0 + j * 8 + 2 * c + (e & 1);
                    bool msk = (mode == 0) ? (wk_s[0][kc] != wq_s[qr])
                                           : (kb * KBL + kc >= nbv);
                    int ri = i * 2 + (e >> 1);
                    float ev = msk ? 0.f : __expf(s);
                    sacc[i][j][e] = ev * idr[ri];
                }
        __syncthreads();              // all warps done reading Kh0
        // store P (half) into Kh0 region
#pragma unroll
        for (int i = 0; i < 2; i++)
#pragma unroll
            for (int j = 0; j < 4; j++) {
                int qr = wq0 + i * 16 + g;
                int kc = wk0 + j * 8 + 2 * c;
                *(__half2*)&Ph[qr][kc] =
                    __floats2half2_rn(sacc[i][j][0], sacc[i][j][1]);
                *(__half2*)&Ph[qr + 8][kc] =
                    __floats2half2_rn(sacc[i][j][2], sacc[i][j][3]);
            }
        __syncthreads();
        if (tid < KBL) {
            float cs = 0.f;
#pragma unroll 8
            for (int qq = 0; qq < QT; qq++) cs += __half2float(Ph[qq][tid]);
            colpart[((long)bh * NQT + qt) * cT + kb * KBL + tid] = cs;
        }
        // out += P * V  (tf32; P half is exact in tf32)
#pragma unroll
        for (int kk = 0; kk < 8; kk++) {
            unsigned af[2][4], bf[4][2];
#pragma unroll
            for (int i = 0; i < 2; i++) {
                int r0 = wq0 + i * 16 + g;
                af[i][0] = __float_as_uint(__half2float(Ph[r0][kk * 8 + c]));
                af[i][1] = __float_as_uint(__half2float(Ph[r0 + 8][kk * 8 + c]));
                af[i][2] = __float_as_uint(__half2float(Ph[r0][kk * 8 + c + 4]));
                af[i][3] = __float_as_uint(__half2float(Ph[r0 + 8][kk * 8 + c + 4]));
            }
#pragma unroll
            for (int j = 0; j < 4; j++) {
                int n = wk0 + j * 8 + g;
                bf[j][0] = __float_as_uint(Vs[kk * 8 + c][n]);
                bf[j][1] = __float_as_uint(Vs[kk * 8 + c + 4][n]);
            }
#pragma unroll
            for (int i = 0; i < 2; i++)
#pragma unroll
                for (int j = 0; j < 4; j++)
                    mma_tf32(oacc[i][j][0], oacc[i][j][1], oacc[i][j][2], oacc[i][j][3],
                             af[i][0], af[i][1], af[i][2], af[i][3],
                             bf[j][0], bf[j][1]);
        }
        __syncthreads();
    }

#pragma unroll
    for (int i = 0; i < 2; i++)
#pragma unroll
        for (int j = 0; j < 4; j++) {
            int qg = q0 + wq0 + i * 16 + g;
            int dh = wk0 + j * 8 + 2 * c;
            long o0 = ((long)b * cT + qg) * cF + (bh & 7) * cDH + dh;
            *(__half2*)&AO[o0] = __floats2half2_rn(oacc[i][j][0], oacc[i][j][1]);
            *(__half2*)&AO[o0 + 8L * cF] = __floats2half2_rn(oacc[i][j][2], oacc[i][j][3]);
        }
}

// -------------------- colsum partial reduction -> score --------------------
__global__ void colreduce(const float* __restrict__ cp, float* __restrict__ outv,
                          float scale) {
    int t = blockIdx.x * 256 + threadIdx.x;
    if (t >= BT) return;
    int b = t / cT, k = t - b * cT;
    float s = 0.f;
    for (int h = 0; h < cH; h++)
#pragma unroll
        for (int q = 0; q < NQT; q++)
            s += cp[(((long)(b * cH + h)) * NQT + q) * cT + k];
    outv[t] = s * scale;
}

// ------------------- window aggregation: pre[b,w,:] ------------------------
__global__ void pre_kernel(const float* __restrict__ lx, const float* __restrict__ ls,
                           const int* __restrict__ nbarr, const int* __restrict__ ws,
                           float* __restrict__ pre) {
    int b = blockIdx.y, w = blockIdx.x, tid = threadIdx.x;
    float4 acc = make_float4(0.f, 0.f, 0.f, 0.f);
    if (w < nbarr[b]) {
        int s = ws[b * (cT + 1) + w];
        int e = ws[b * (cT + 1) + w + 1];
        for (int t = s; t < e; t++) {
            float sc = __ldg(&ls[b * cT + t]);
            float4 v = ((const float4*)(lx + ((long)b * cT + t) * cF))[tid];
            acc.x = fmaf(v.x, sc, acc.x); acc.y = fmaf(v.y, sc, acc.y);
            acc.z = fmaf(v.z, sc, acc.z); acc.w = fmaf(v.w, sc, acc.w);
        }
    }
    ((float4*)(pre + ((long)b * cT + w) * cF))[tid] = acc;
}

// --------------------------- misc elementwise ------------------------------
__global__ void final_data(const float* __restrict__ lx, const float* __restrict__ gy,
                           const int* __restrict__ wid, float* __restrict__ outd) {
    long i = blockIdx.x;
    int b = (int)(i / cT);
    int w = wid[i];
    float4 a = ((const float4*)(lx + i * cF))[threadIdx.x];
    float4 g = ((const float4*)(gy + ((long)b * cT + w) * cF))[threadIdx.x];
    a.x += g.x; a.y += g.y; a.z += g.z; a.w += g.w;
    ((float4*)(outd + i * cF))[threadIdx.x] = a;
}

__global__ void final_attn(const float* __restrict__ ls, const float* __restrict__ h2,
                           const int* __restrict__ wid, float* __restrict__ outa) {
    int b = blockIdx.x, tid = threadIdx.x;
    float xv[3];
#pragma unroll
    for (int i = 0; i < 3; i++) {
        int t = tid + i * 256;
        xv[i] = ls[b * cT + t] * h2[b * cT + wid[b * cT + t]];
    }
    float mx = redMax256(fmaxf(fmaxf(xv[0], xv[1]), xv[2]));
    float e[3];
    float s = 0.f;
#pragma unroll
    for (int i = 0; i < 3; i++) { e[i] = expf(xv[i] - mx); s += e[i]; }
    s = redSum256(s);
    float inv = 1.0f / s;
#pragma unroll
    for (int i = 0; i < 3; i++) outa[b * cT + tid + i * 256] = e[i] * inv;
}

// ------------------------------ host side ----------------------------------
static void run_transformer(const __half* xin_h, const float* xin_f,
                            const __half* W,
                            float* yout, float* score, int mode,
                            __half* qk, float* v, __half* ao, float* pj,
                            __half* y, __half* h, float* colpart,
                            const int* wid, const int* nb,
                            const float* wise_for_final) {
    // QK projection -> half [BT][1024]
    gemm_h<128, 128, 128, 2, 2, false, 2><<<dim3(SQK / 128, BT / 128, 1), 128>>>(
        xin_h, W + OFF_QKV, qk, cF, cF, cF, SQK, 1.f);
    // V projection -> float tf32-rounded [BT][512]
    gemm_h<128, 128, 128, 2, 2, false, 1><<<dim3(cF / 128, BT / 128, 1), 128>>>(
        xin_h, W + OFF_QKV + (long)SQK * cF, v, cF, cF, cF, cF, 1.f);
    attn_fused<<<dim3(NQT, cB * cH), 128>>>(qk, v, ao, colpart, wid, nb, mode);
    gemm_h<128, 128, 128, 2, 2, false, 0><<<dim3(cF / 128, BT / 128, 1), 128>>>(
        ao, W + OFF_WO, pj, cF, cF, cF, cF, 1.f);
    colreduce<<<(BT + 255) / 256, 256>>>(colpart, score, 1.0f / (cH * cT));
    // y = LN(xin_f + pj): float copy in yout (residual), half twin for FFN
    ln_ff<<<BT, 128>>>(xin_f, pj, yout, y, nullptr);
    gemm_h<128, 128, 128, 2, 2, true, 2><<<dim3(cFF / 128, BT / 128, 1), 128>>>(
        y, W + OFF_W1, h, cF, cF, cF, cFF, 1.f);
    gemm_h<128, 128, 128, 2, 2, false, 0><<<dim3(cF / 128, BT / 128, 1), 128>>>(
        h, W + OFF_W2, pj, cFF, cFF, cFF, cF, 1.f);
    ln_ff<<<BT, 128>>>(yout, pj, yout, nullptr, wise_for_final);
}

extern "C" void kernel_launch(void* const* d_in, const int* in_sizes, int n_in,
                              void* d_out, int out_size) {
    (void)in_sizes; (void)n_in; (void)out_size;
    const float* x   = (const float*)d_in[0];
    const float* hs  = (const float*)d_in[1];
    const float* msk = (const float*)d_in[2];

    float* out      = (float*)d_out;
    float* out_thr  = out + (long)BT * cF;
    float* out_attn = out_thr + cB;

    __half *xl, *qk, *ao, *y, *h, *wt;
    float *v, *pj, *lx, *gy, *pre, *xf, *ls, *h2, *wise, *cp;
    int *wid, *nb, *ws;
    cudaGetSymbolAddress((void**)&xl,   g_xl);
    cudaGetSymbolAddress((void**)&qk,   g_qk);
    cudaGetSymbolAddress((void**)&v,    g_v);
    cudaGetSymbolAddress((void**)&ao,   g_ao);
    cudaGetSymbolAddress((void**)&pj,   g_pj);
    cudaGetSymbolAddress((void**)&y,    g_y);
    cudaGetSymbolAddress((void**)&h,    g_h);
    cudaGetSymbolAddress((void**)&lx,   g_lx);
    cudaGetSymbolAddress((void**)&gy,   g_gy);
    cudaGetSymbolAddress((void**)&pre,  g_pre);
    cudaGetSymbolAddress((void**)&xf,   g_xf);
    cudaGetSymbolAddress((void**)&ls,   g_ls);
    cudaGetSymbolAddress((void**)&h2,   g_h2);
    cudaGetSymbolAddress((void**)&wise, g_wise);
    cudaGetSymbolAddress((void**)&cp,   g_cp);
    cudaGetSymbolAddress((void**)&wt,   g_wt);
    cudaGetSymbolAddress((void**)&wid,  g_wid);
    cudaGetSymbolAddress((void**)&nb,   g_nb);
    cudaGetSymbolAddress((void**)&ws,   g_ws);

    // 0. transpose + fp16-convert all 12 weights
    for (int t = 0; t < 2; t++) {
        __half* tb = wt + (long)t * WSET;
        for (int jj = 0; jj < 3; jj++)
            cvtT<<<dim3(cF / 32, cF / 32), dim3(32, 8)>>>(
                (const float*)d_in[3 + t * 6 + jj],
                tb + OFF_QKV + (long)jj * cF * cF, cF, cF);
        cvtT<<<dim3(cF / 32, cF / 32), dim3(32, 8)>>>(
            (const float*)d_in[3 + t * 6 + 3], tb + OFF_WO, cF, cF);
        cvtT<<<dim3(cF / 32, cFF / 32), dim3(32, 8)>>>(
            (const float*)d_in[3 + t * 6 + 4], tb + OFF_W1, cF, cFF);
        cvtT<<<dim3(cFF / 32, cF / 32), dim3(32, 8)>>>(
            (const float*)d_in[3 + t * 6 + 5], tb + OFF_W2, cFF, cF);
    }

    // 1. masks
    masks_kernel<<<cB, 256>>>(hs, msk, out_thr, wid, nb, ws, wise);
    // 2. xf = LN(x) float, xl = half twin
    ln_ff<<<BT, 128>>>(x, nullptr, xf, xl, nullptr);
    // 3. local transformer (wise fused into its final LN)
    run_transformer(xl, xf, wt, lx, ls, /*mode=*/0,
                    qk, v, ao, pj, y, h, cp, wid, nb, wise);
    // 5. pre aggregation
    pre_kernel<<<dim3(cT, cB), 128>>>(lx, ls, nb, ws, pre);
    // 6. xf = LN(pre) float, xl = half twin
    ln_ff<<<BT, 128>>>(pre, nullptr, xf, xl, nullptr);
    // 7. global transformer
    run_transformer(xl, xf, wt + WSET, gy, h2, /*mode=*/1,
                    qk, v, ao, pj, y, h, cp, wid, nb, nullptr);
    // 8/9. outputs
    final_data<<<BT, 128>>>(lx, gy, wid, out);
    final_attn<<<cB, 256>>>(ls, h2, wid, out_attn);
}